// round 6
// baseline (speedup 1.0000x reference)
#include <cuda_runtime.h>
#include <cuda_bf16.h>
#include <cstdint>

// ---------------------------------------------------------------------------
// MinkUNet backbone, round 5: tcgen05 bf16 double-double implicit GEMM with
// producer-side splitting. Feature maps are stored as interleaved bf16 hi/lo
// (16B hi chunk + 16B lo chunk per 8 elements); the gather loop reads them
// directly into swizzled smem with no conversion math. fp32 copies exist only
// where consumed as fp32 (residual inputs, final projection input).
// ---------------------------------------------------------------------------

#define KN0 100000
#define KN1 50000
#define KN2 25000
#define KN3 12500

// fp32 scratch (only where needed as fp32)
__device__ float g_x0a_f[KN0 * 32];
__device__ float g_x1a_f[KN1 * 64];
__device__ float g_x2a_f[KN2 * 128];
__device__ float g_x3a_f[KN3 * 256];
__device__ float g_u0_f[KN0 * 96];

// interleaved bf16 hi/lo scratch: N*C/4 uint4 per map (== fp32 byte size)
__device__ uint4 g_x0a_i[KN0 * 32 / 4];
__device__ uint4 g_x0b_i[KN0 * 32 / 4];
__device__ uint4 g_x1a_i[KN1 * 64 / 4];
__device__ uint4 g_x1b_i[KN1 * 64 / 4];
__device__ uint4 g_x2a_i[KN2 * 128 / 4];
__device__ uint4 g_x2b_i[KN2 * 128 / 4];
__device__ uint4 g_x3a_i[KN3 * 256 / 4];
__device__ uint4 g_x3b_i[KN3 * 256 / 4];
__device__ uint4 g_u2_i[KN2 * 256 / 4];
__device__ uint4 g_u1_i[KN1 * 128 / 4];

#define WDECL(name, npad, kpad) \
    __device__ uint4 name##h[(npad) * (kpad) / 8]; \
    __device__ uint4 name##l[(npad) * (kpad) / 8];
WDECL(w_b0, 32, 896)
WDECL(w_d1, 64, 256)
WDECL(w_b1, 64, 1728)
WDECL(w_d2, 128, 512)
WDECL(w_b2, 128, 3456)
WDECL(w_d3, 256, 1024)
WDECL(w_b3, 256, 6912)
WDECL(w_u2, 256, 384)
WDECL(w_u1, 128, 320)
WDECL(w_u0, 128, 192)

#define A_CONV 0
#define A_CONCAT 1
#define E_RELU 0
#define E_RES_RELU 1

#if defined(__CUDA_ARCH__) && !defined(__CUDA_ARCH_FEAT_SM103_ALL)
#define NO_TC 1
#endif

// ---------------- PTX helpers ----------------
__device__ __forceinline__ uint32_t smem_u32(const void* p) {
    uint32_t a;
    asm("{ .reg .u64 t; cvta.to.shared.u64 t, %1; cvt.u32.u64 %0, t; }" : "=r"(a) : "l"(p));
    return a;
}
__device__ __forceinline__ uint32_t elect_one() {
    uint32_t p;
    asm volatile("{ .reg .pred p; elect.sync _|p, 0xFFFFFFFF; selp.b32 %0, 1, 0, p; }" : "=r"(p));
    return p;
}
#define MBAR_INIT(a, c) asm volatile("mbarrier.init.shared.b64 [%0], %1;" :: "r"(a), "r"(c) : "memory")
#define MBAR_INVAL(a)   asm volatile("mbarrier.inval.shared.b64 [%0];" :: "r"(a) : "memory")
#define MBAR_WAIT(a, ph) do { \
    uint32_t _m = (a), _p = (ph), _d; \
    asm volatile("{ .reg .pred p; mbarrier.try_wait.parity.acquire.cta.shared::cta.b64 p, [%1], %2; selp.b32 %0,1,0,p; }" \
                 : "=r"(_d) : "r"(_m), "r"(_p) : "memory"); \
    if (!_d) { \
        asm volatile("{ .reg .pred P1; WL_%=: mbarrier.try_wait.parity.acquire.cta.shared::cta.b64 P1, [%0], %1, 0x989680; @P1 bra.uni WD_%=; bra.uni WL_%=; WD_%=: }" \
                     :: "r"(_m), "r"(_p) : "memory"); \
    } } while (0)
#define FENCE_ASYNC() asm volatile("fence.proxy.async.shared::cta;" ::: "memory")

#ifdef NO_TC
#define TC_ALLOC(sa, n)   ((void)0)
#define TC_DEALLOC(t, n)  ((void)0)
#define TC_RELINQ()       ((void)0)
#define TC_COMMIT(a)      ((void)0)
#define TC_FENCE_AFTER()  ((void)0)
#define TC_FENCE_BEFORE() ((void)0)
#define TC_WAIT_LD()      ((void)0)
#define TC_LD_X32(r, ta)  do { _Pragma("unroll") for (int _i = 0; _i < 32; ++_i) (r)[_i] = 0u; } while (0)
__device__ __forceinline__ void mma_bf16_ss(uint32_t, uint64_t, uint64_t, uint32_t, uint32_t) {}
#else
#define TC_ALLOC(sa, n)   asm volatile("tcgen05.alloc.cta_group::1.sync.aligned.shared::cta.b32 [%0], %1;" :: "r"(sa), "r"(n) : "memory")
#define TC_DEALLOC(t, n)  asm volatile("tcgen05.dealloc.cta_group::1.sync.aligned.b32 %0, %1;" :: "r"(t), "r"(n))
#define TC_RELINQ()       asm volatile("tcgen05.relinquish_alloc_permit.cta_group::1.sync.aligned;")
#define TC_COMMIT(a)      asm volatile("tcgen05.commit.cta_group::1.mbarrier::arrive::one.shared::cluster.b64 [%0];" :: "r"(a) : "memory")
#define TC_FENCE_AFTER()  asm volatile("tcgen05.fence::after_thread_sync;" ::: "memory")
#define TC_FENCE_BEFORE() asm volatile("tcgen05.fence::before_thread_sync;" ::: "memory")
#define TC_WAIT_LD()      asm volatile("tcgen05.wait::ld.sync.aligned;" ::: "memory")
#define TC_LD_X32(r, ta) \
    asm volatile("tcgen05.ld.sync.aligned.32x32b.x32.b32 {%0,%1,%2,%3,%4,%5,%6,%7,%8,%9,%10,%11,%12,%13,%14,%15,%16,%17,%18,%19,%20,%21,%22,%23,%24,%25,%26,%27,%28,%29,%30,%31}, [%32];" \
        : "=r"((r)[0]), "=r"((r)[1]), "=r"((r)[2]), "=r"((r)[3]), "=r"((r)[4]), "=r"((r)[5]), "=r"((r)[6]), "=r"((r)[7]), \
          "=r"((r)[8]), "=r"((r)[9]), "=r"((r)[10]), "=r"((r)[11]), "=r"((r)[12]), "=r"((r)[13]), "=r"((r)[14]), "=r"((r)[15]), \
          "=r"((r)[16]), "=r"((r)[17]), "=r"((r)[18]), "=r"((r)[19]), "=r"((r)[20]), "=r"((r)[21]), "=r"((r)[22]), "=r"((r)[23]), \
          "=r"((r)[24]), "=r"((r)[25]), "=r"((r)[26]), "=r"((r)[27]), "=r"((r)[28]), "=r"((r)[29]), "=r"((r)[30]), "=r"((r)[31]) \
        : "r"(ta))
__device__ __forceinline__ void mma_bf16_ss(uint32_t d, uint64_t ad, uint64_t bd,
                                            uint32_t idesc, uint32_t acc) {
    asm volatile(
        "{ .reg .pred p; setp.ne.u32 p, %5, 0;\n\t"
        "tcgen05.mma.cta_group::1.kind::f16 [%0], %1, %2, %3, {%4,%4,%4,%4}, p; }"
        :: "r"(d), "l"(ad), "l"(bd), "r"(idesc), "r"(0u), "r"(acc) : "memory");
}
#endif

// SW128 K-major descriptor: layout=2, version=1, SBO=64, LBO=1
__device__ __forceinline__ uint64_t mk_desc(uint32_t addr) {
    const uint64_t base = (uint64_t(2) << 61) | (uint64_t(1) << 46) |
                          (uint64_t(64) << 32) | (uint64_t(1) << 16);
    return base | ((uint64_t)(addr >> 4) & 0x3FFF);
}
__device__ __forceinline__ uint32_t sw128(uint32_t off) {
    return off ^ ((off >> 3) & 0x70);
}
// split 2 floats into packed hi/lo bf16x2 (memory order x0 then x1)
__device__ __forceinline__ void split2(float x0, float x1, uint32_t& h, uint32_t& l) {
    uint32_t hp;
    asm("cvt.rn.satfinite.bf16x2.f32 %0, %1, %2;" : "=r"(hp) : "f"(x1), "f"(x0));
    float h0 = __uint_as_float(hp << 16);
    float h1 = __uint_as_float(hp & 0xFFFF0000u);
    float l0 = x0 - h0, l1 = x1 - h1;
    uint32_t lp;
    asm("cvt.rn.satfinite.bf16x2.f32 %0, %1, %2;" : "=r"(lp) : "f"(l1), "f"(l0));
    h = hp; l = lp;
}

// ---------------- tensor-core gather GEMM ----------------
// Tile: M=128 x N=NT, BK=64 (128B bf16 rows), 2-stage pipeline.
// Feature inputs are interleaved bf16 hi/lo uint4 arrays.
template <int NT, int AMODE, int EPI>
__global__ __launch_bounds__(256, 1) void tc_gemm(
    const uint4* __restrict__ fAi, const uint4* __restrict__ fBi,
    const int* __restrict__ idx,
    const uint4* __restrict__ Wh, const uint4* __restrict__ Wl,
    const float* __restrict__ res, float* __restrict__ out,
    uint4* __restrict__ outI,
    int M, int Cout, int Kdim, int Kpad, int Cin, int KN, int Ca)
{
    constexpr int AB = 128 * 128;          // bytes per A subtile
    constexpr int BB = NT * 128;           // bytes per B subtile
    constexpr int STAGE = 2 * AB + 2 * BB;
    constexpr uint32_t IDESC =
        (1u << 4) | (1u << 7) | (1u << 10) | ((NT / 8) << 17) | (8u << 24);

    extern __shared__ char dsm[];
    __shared__ uint32_t s_tmem[1];
    __shared__ __align__(16) unsigned long long s_mbar[2];

    const int tid = threadIdx.x;
    const int wid = tid >> 5;
    const int lid = tid & 31;

    const uint32_t raw = smem_u32(dsm);
    const uint32_t sb = (raw + 1023u) & ~1023u;
    char* tiles = dsm + (sb - raw);

    const uint32_t mb0 = smem_u32(&s_mbar[0]);
    const uint32_t mb1 = mb0 + 8;
    const uint32_t tptr = smem_u32(&s_tmem[0]);

    if (wid == 0) TC_ALLOC(tptr, 256);
    if (tid == 0) { MBAR_INIT(mb0, 1); MBAR_INIT(mb1, 1); }
    __syncthreads();
    const uint32_t tmem = s_tmem[0];

    const int m0 = blockIdx.x * 128;
    const int ntile = Kpad / 64;
    const int ar = tid >> 1;              // A row 0..127
    const int ac0 = (tid & 1) * 4;        // first of 4 chunks (16B each)
    const int m = m0 + ar;

    const uint64_t dAh0 = mk_desc(sb);
    const uint64_t dAl0 = mk_desc(sb + AB);
    const uint64_t dBh0 = mk_desc(sb + 2 * AB);
    const uint64_t dBl0 = mk_desc(sb + 2 * AB + BB);

    int use0 = 0, use1 = 0;

    for (int t = 0; t < ntile; ++t) {
        const int b = t & 1;
        const uint32_t mb = b ? mb1 : mb0;
        const int use = b ? use1 : use0;
        if (use > 0) MBAR_WAIT(mb, (use - 1) & 1);

        char* Ah = tiles + b * STAGE;
        char* Al = Ah + AB;
        char* Bh = tiles + b * STAGE + 2 * AB;
        char* Bl = Bh + BB;
        const int kt = t * 64;

        // ---- gather A (pre-split interleaved bf16) ----
#pragma unroll
        for (int c = ac0; c < ac0 + 4; ++c) {
            const int kk = kt + c * 8;
            uint4 hv = make_uint4(0u, 0u, 0u, 0u), lv = hv;
            if (m < M && kk < Kdim) {
                const uint4* src;
                size_t goff;
                if (AMODE == A_CONV) {
                    const int kOff = kk / Cin;
                    const int ci = kk - kOff * Cin;
                    const int g = idx[(size_t)m * KN + kOff];
                    src = fAi; goff = ((size_t)g * Cin + ci) >> 3;
                } else {  // A_CONCAT
                    if (kk < Ca) {
                        const int g = idx[m];
                        src = fAi; goff = ((size_t)g * Ca + kk) >> 3;
                    } else {
                        src = fBi; goff = ((size_t)m * (Kdim - Ca) + (kk - Ca)) >> 3;
                    }
                }
                hv = src[2 * goff];
                lv = src[2 * goff + 1];
            }
            const uint32_t sw = sw128((uint32_t)(ar * 128 + c * 16));
            *reinterpret_cast<uint4*>(Ah + sw) = hv;
            *reinterpret_cast<uint4*>(Al + sw) = lv;
        }
        // ---- load B (pre-split, padded: unconditional) ----
        const int kq = kt / 8;
        const int kpq = Kpad / 8;
        for (int i = tid; i < NT * 8; i += 256) {
            const int n = i >> 3, j = i & 7;
            const uint4 h = Wh[(size_t)n * kpq + kq + j];
            const uint4 l = Wl[(size_t)n * kpq + kq + j];
            const uint32_t sw = sw128((uint32_t)(n * 128 + j * 16));
            *reinterpret_cast<uint4*>(Bh + sw) = h;
            *reinterpret_cast<uint4*>(Bl + sw) = l;
        }
        FENCE_ASYNC();
        __syncthreads();

        // ---- issue MMAs ----
        if (wid == 0 && elect_one()) {
            const uint64_t so = (uint64_t)b * (STAGE >> 4);
#pragma unroll
            for (int ks = 0; ks < 4; ++ks) {
                const uint64_t o = so + ks * 2;
                mma_bf16_ss(tmem, dAh0 + o, dBh0 + o, IDESC, !(t == 0 && ks == 0));
                mma_bf16_ss(tmem, dAh0 + o, dBl0 + o, IDESC, 1u);
                mma_bf16_ss(tmem, dAl0 + o, dBh0 + o, IDESC, 1u);
            }
            TC_COMMIT(mb);
        }
        if (b) use1++; else use0++;
    }
    if (use0 > 0) MBAR_WAIT(mb0, (use0 - 1) & 1);
    if (use1 > 0) MBAR_WAIT(mb1, (use1 - 1) & 1);
    TC_FENCE_AFTER();

    // ---- epilogue: both warpgroups read TMEM (subpartition = wid&3) ----
    const int sub = wid & 3;
    const int half = wid >> 2;
    const int mr = m0 + sub * 32 + lid;
    constexpr int CH = NT / 32;
    for (int c = half; c < CH; c += 2) {
        uint32_t r[32];
        TC_LD_X32(r, tmem + c * 32 + ((uint32_t)sub << 21));
        TC_WAIT_LD();
        const int nb = c * 32;
        if (mr < M && nb < Cout) {
#pragma unroll
            for (int j = 0; j < 32; j += 8) {
                float v[8];
#pragma unroll
                for (int q = 0; q < 8; ++q)
                    v[q] = fmaxf(__uint_as_float(r[j + q]), 0.f);
                if (EPI == E_RES_RELU) {
                    const float4 r0 = *reinterpret_cast<const float4*>(
                        res + (size_t)mr * Cout + nb + j);
                    const float4 r1 = *reinterpret_cast<const float4*>(
                        res + (size_t)mr * Cout + nb + j + 4);
                    v[0] += r0.x; v[1] += r0.y; v[2] += r0.z; v[3] += r0.w;
                    v[4] += r1.x; v[5] += r1.y; v[6] += r1.z; v[7] += r1.w;
                }
                if (out) {
                    float4 o0 = make_float4(v[0], v[1], v[2], v[3]);
                    float4 o1 = make_float4(v[4], v[5], v[6], v[7]);
                    *reinterpret_cast<float4*>(out + (size_t)mr * Cout + nb + j) = o0;
                    *reinterpret_cast<float4*>(out + (size_t)mr * Cout + nb + j + 4) = o1;
                }
                if (outI) {
                    uint4 hv, lv;
                    split2(v[0], v[1], hv.x, lv.x);
                    split2(v[2], v[3], hv.y, lv.y);
                    split2(v[4], v[5], hv.z, lv.z);
                    split2(v[6], v[7], hv.w, lv.w);
                    const size_t goff = ((size_t)mr * Cout + nb + j) >> 3;
                    outI[2 * goff] = hv;
                    outI[2 * goff + 1] = lv;
                }
            }
        }
    }
    TC_FENCE_BEFORE();
    __syncthreads();
    if (tid == 0) { MBAR_INVAL(mb0); MBAR_INVAL(mb1); }
    __syncthreads();
    if (wid == 0) { TC_RELINQ(); TC_DEALLOC(tmem, 256); }
}

// ---------------- weight conversion: W[K][Cout] fp32 -> [Npad][Kpad] bf16 hi/lo
__global__ void conv_w(const float* __restrict__ W, uint4* __restrict__ Wh,
                       uint4* __restrict__ Wl, int Kdim, int Cout, int Kpad, int Npad)
{
    const int i = blockIdx.x * 256 + threadIdx.x;
    const int total = Npad * Kpad;
    if (i >= total) return;
    const int n = i / Kpad, k = i - n * Kpad;
    float x = 0.f;
    if (n < Cout && k < Kdim) x = W[(size_t)k * Cout + n];
    const __nv_bfloat16 h = __float2bfloat16_rn(x);
    const float hf = __bfloat162float(h);
    const __nv_bfloat16 l = __float2bfloat16_rn(x - hf);
    reinterpret_cast<__nv_bfloat16*>(Wh)[i] = h;
    reinterpret_cast<__nv_bfloat16*>(Wl)[i] = l;
}

// ---------------- SIMT GEMM for the final seed projection ----------------
template <int BM, int BN, int BK, int TM, int TN>
__global__ __launch_bounds__((BM / TM) * (BN / TN), 2) void gemm_final(
    const float* __restrict__ fA, const int* __restrict__ idx,
    const float* __restrict__ W, float* __restrict__ out,
    int M, int Cout, int Kdim)
{
    constexpr int THREADS = (BM / TM) * (BN / TN);
    constexpr int BMP = BM + 4;
    constexpr int A4 = BM * BK / 4;
    constexpr int B4 = BK * BN / 4;
    constexpr int NA = (A4 + THREADS - 1) / THREADS;
    constexpr int NB = (B4 + THREADS - 1) / THREADS;
    constexpr int BK4 = BK / 4;
    constexpr int BN4 = BN / 4;

    __shared__ __align__(16) float As[2][BK][BMP];
    __shared__ __align__(16) float Bs[2][BK][BN];

    const int tid = threadIdx.x;
    const int m0 = blockIdx.x * BM;
    const int n0 = blockIdx.y * BN;
    const int tx = tid % (BN / TN);
    const int ty = tid / (BN / TN);

    float4 ra[NA], rb[NB];
    float acc[TM][TN] = {};
    const int ntile = Kdim / BK;

    auto load_tile = [&](int it) {
        const int kt = it * BK;
#pragma unroll
        for (int t = 0; t < NA; ++t) {
            const int i4 = tid + t * THREADS;
            if (i4 < A4) {
                const int row = i4 / BK4;
                const int c4 = (i4 - row * BK4) * 4;
                const int m = m0 + row;
                float4 v = make_float4(0.f, 0.f, 0.f, 0.f);
                if (m < M) {
                    const int g = idx[m];
                    v = *reinterpret_cast<const float4*>(fA + (size_t)g * Kdim + kt + c4);
                }
                ra[t] = v;
            }
        }
#pragma unroll
        for (int t = 0; t < NB; ++t) {
            const int i4 = tid + t * THREADS;
            if (i4 < B4) {
                const int row = i4 / BN4;
                const int c = (i4 - row * BN4) * 4;
                rb[t] = *reinterpret_cast<const float4*>(W + (size_t)(kt + row) * Cout + n0 + c);
            }
        }
    };
    auto store_tile = [&](int buf) {
#pragma unroll
        for (int t = 0; t < NA; ++t) {
            const int i4 = tid + t * THREADS;
            if (i4 < A4) {
                const int row = i4 / BK4;
                const int c4 = (i4 - row * BK4) * 4;
                As[buf][c4 + 0][row] = ra[t].x;
                As[buf][c4 + 1][row] = ra[t].y;
                As[buf][c4 + 2][row] = ra[t].z;
                As[buf][c4 + 3][row] = ra[t].w;
            }
        }
#pragma unroll
        for (int t = 0; t < NB; ++t) {
            const int i4 = tid + t * THREADS;
            if (i4 < B4) {
                const int row = i4 / BN4;
                const int c = (i4 - row * BN4) * 4;
                *reinterpret_cast<float4*>(&Bs[buf][row][c]) = rb[t];
            }
        }
    };

    load_tile(0); store_tile(0); __syncthreads();
    int buf = 0;
    for (int it = 0; it < ntile; ++it) {
        if (it + 1 < ntile) load_tile(it + 1);
#pragma unroll
        for (int kk = 0; kk < BK; ++kk) {
            float a[TM], b[TN];
#pragma unroll
            for (int i = 0; i < TM; i += 4) {
                const float4 v = *reinterpret_cast<const float4*>(&As[buf][kk][ty * TM + i]);
                a[i] = v.x; a[i + 1] = v.y; a[i + 2] = v.z; a[i + 3] = v.w;
            }
#pragma unroll
            for (int j = 0; j < TN; j += 4) {
                const float4 v = *reinterpret_cast<const float4*>(&Bs[buf][kk][tx * TN + j]);
                b[j] = v.x; b[j + 1] = v.y; b[j + 2] = v.z; b[j + 3] = v.w;
            }
#pragma unroll
            for (int i = 0; i < TM; ++i)
#pragma unroll
                for (int j = 0; j < TN; ++j)
                    acc[i][j] = fmaf(a[i], b[j], acc[i][j]);
        }
        if (it + 1 < ntile) store_tile(buf ^ 1);
        __syncthreads();
        buf ^= 1;
    }
#pragma unroll
    for (int i = 0; i < TM; ++i) {
        const int mm = m0 + ty * TM + i;
        if (mm >= M) continue;
        const int bb = mm >> 10, ss = mm & 1023;
#pragma unroll
        for (int j = 0; j < TN; ++j) {
            const int n = n0 + tx * TN + j;
            out[((size_t)bb * Cout + n) * 1024 + ss] = acc[i][j];
        }
    }
}

// Stem: Cin=3 -> dedicated SIMT kernel; writes fp32 + interleaved bf16.
__global__ __launch_bounds__(256) void stem_k(
    const float* __restrict__ feats, const int* __restrict__ nbr,
    const float* __restrict__ W, float* __restrict__ out,
    uint4* __restrict__ outI, int M)
{
    __shared__ float sW[27 * 3 * 32];
    __shared__ float sg[8][81];
    __shared__ int   sidx[8][27];
    const int tid = threadIdx.x;
    const int m0 = blockIdx.x * 8;

    for (int i = tid; i < 27 * 96; i += 256) sW[i] = W[i];
    for (int i = tid; i < 8 * 27; i += 256) {
        const int r = i / 27, k = i % 27;
        const int m = m0 + r;
        sidx[r][k] = (m < M) ? nbr[(size_t)m * 27 + k] : 0;
    }
    __syncthreads();
    for (int i = tid; i < 8 * 81; i += 256) {
        const int r = i / 81, j = i % 81;
        sg[r][j] = feats[(size_t)sidx[r][j / 3] * 3 + (j % 3)];
    }
    __syncthreads();
    const int r = tid >> 5, co = tid & 31;
    const int m = m0 + r;
    float acc = 0.f;
#pragma unroll
    for (int j = 0; j < 81; ++j)
        acc = fmaf(sg[r][j], sW[j * 32 + co], acc);
    if (m < M) {
        const float v = fmaxf(acc, 0.f);
        out[(size_t)m * 32 + co] = v;
        const __nv_bfloat16 h = __float2bfloat16_rn(v);
        const __nv_bfloat16 l = __float2bfloat16_rn(v - __bfloat162float(h));
        __nv_bfloat16* bi = reinterpret_cast<__nv_bfloat16*>(outI);
        const size_t goff = ((size_t)m * 32 + co) >> 3;
        const int w = co & 7;
        bi[goff * 16 + w] = h;
        bi[goff * 16 + 8 + w] = l;
    }
}

static float* symf(const void* s) { void* p = nullptr; cudaGetSymbolAddress(&p, s); return (float*)p; }
static uint4* sym4(const void* s) { void* p = nullptr; cudaGetSymbolAddress(&p, s); return (uint4*)p; }

extern "C" void kernel_launch(void* const* d_in, const int* in_sizes, int n_in,
                              void* d_out, int out_size)
{
    const float* feats  = (const float*)d_in[0];
    const int* nbr0     = (const int*)d_in[1];
    const int* nbr1     = (const int*)d_in[2];
    const int* nbr2     = (const int*)d_in[3];
    const int* nbr3     = (const int*)d_in[4];
    const int* down1    = (const int*)d_in[5];
    const int* down2    = (const int*)d_in[6];
    const int* down3    = (const int*)d_in[7];
    const int* up2      = (const int*)d_in[8];
    const int* up1      = (const int*)d_in[9];
    const int* up0      = (const int*)d_in[10];
    const int* seed_idx = (const int*)d_in[11];
    const float* W_stem = (const float*)d_in[12];
    const float* W_b0   = (const float*)d_in[13];
    const float* W_d1   = (const float*)d_in[14];
    const float* W_b1   = (const float*)d_in[15];
    const float* W_d2   = (const float*)d_in[16];
    const float* W_b2   = (const float*)d_in[17];
    const float* W_d3   = (const float*)d_in[18];
    const float* W_b3   = (const float*)d_in[19];
    const float* W_u2   = (const float*)d_in[20];
    const float* W_u1   = (const float*)d_in[21];
    const float* W_u0   = (const float*)d_in[22];
    const float* W_out  = (const float*)d_in[23];
    float* out = (float*)d_out;

    float* x0a_f = symf(g_x0a_f); float* x1a_f = symf(g_x1a_f);
    float* x2a_f = symf(g_x2a_f); float* x3a_f = symf(g_x3a_f);
    float* u0_f  = symf(g_u0_f);
    uint4* x0a_i = sym4(g_x0a_i); uint4* x0b_i = sym4(g_x0b_i);
    uint4* x1a_i = sym4(g_x1a_i); uint4* x1b_i = sym4(g_x1b_i);
    uint4* x2a_i = sym4(g_x2a_i); uint4* x2b_i = sym4(g_x2b_i);
    uint4* x3a_i = sym4(g_x3a_i); uint4* x3b_i = sym4(g_x3b_i);
    uint4* u2_i  = sym4(g_u2_i);  uint4* u1_i  = sym4(g_u1_i);

    const int SM32  = (2 * 128 * 128 + 2 * 32 * 128) * 2 + 1024;
    const int SM64  = (2 * 128 * 128 + 2 * 64 * 128) * 2 + 1024;
    const int SM128 = (2 * 128 * 128 + 2 * 128 * 128) * 2 + 1024;
    const int SM256 = (2 * 128 * 128 + 2 * 256 * 128) * 2 + 1024;
    cudaFuncSetAttribute(tc_gemm<32,  A_CONV,   E_RES_RELU>, cudaFuncAttributeMaxDynamicSharedMemorySize, SM32);
    cudaFuncSetAttribute(tc_gemm<64,  A_CONV,   E_RELU>,     cudaFuncAttributeMaxDynamicSharedMemorySize, SM64);
    cudaFuncSetAttribute(tc_gemm<64,  A_CONV,   E_RES_RELU>, cudaFuncAttributeMaxDynamicSharedMemorySize, SM64);
    cudaFuncSetAttribute(tc_gemm<128, A_CONV,   E_RELU>,     cudaFuncAttributeMaxDynamicSharedMemorySize, SM128);
    cudaFuncSetAttribute(tc_gemm<128, A_CONV,   E_RES_RELU>, cudaFuncAttributeMaxDynamicSharedMemorySize, SM128);
    cudaFuncSetAttribute(tc_gemm<128, A_CONCAT, E_RELU>,     cudaFuncAttributeMaxDynamicSharedMemorySize, SM128);
    cudaFuncSetAttribute(tc_gemm<256, A_CONV,   E_RELU>,     cudaFuncAttributeMaxDynamicSharedMemorySize, SM256);
    cudaFuncSetAttribute(tc_gemm<256, A_CONV,   E_RES_RELU>, cudaFuncAttributeMaxDynamicSharedMemorySize, SM256);
    cudaFuncSetAttribute(tc_gemm<256, A_CONCAT, E_RELU>,     cudaFuncAttributeMaxDynamicSharedMemorySize, SM256);

    auto cw = [&](const float* W, uint4* Wh, uint4* Wl, int Kd, int Co, int Kp, int Np) {
        const int total = Np * Kp;
        conv_w<<<(total + 255) / 256, 256>>>(W, Wh, Wl, Kd, Co, Kp, Np);
    };
    cw(W_b0, sym4(w_b0h), sym4(w_b0l),  864,  32,  896,  32);
    cw(W_d1, sym4(w_d1h), sym4(w_d1l),  256,  64,  256,  64);
    cw(W_b1, sym4(w_b1h), sym4(w_b1l), 1728,  64, 1728,  64);
    cw(W_d2, sym4(w_d2h), sym4(w_d2l),  512, 128,  512, 128);
    cw(W_b2, sym4(w_b2h), sym4(w_b2l), 3456, 128, 3456, 128);
    cw(W_d3, sym4(w_d3h), sym4(w_d3l), 1024, 256, 1024, 256);
    cw(W_b3, sym4(w_b3h), sym4(w_b3l), 6912, 256, 6912, 256);
    cw(W_u2, sym4(w_u2h), sym4(w_u2l),  384, 256,  384, 256);
    cw(W_u1, sym4(w_u1h), sym4(w_u1l),  320, 128,  320, 128);
    cw(W_u0, sym4(w_u0h), sym4(w_u0l),  160,  96,  192, 128);

    const int M0 = KN0, M1 = KN1, M2 = KN2, M3 = KN3;
    auto g = [](int M) { return (unsigned)((M + 127) / 128); };

    // ---- encoder ----
    stem_k<<<(M0 + 7) / 8, 256>>>(feats, nbr0, W_stem, x0a_f, x0a_i, M0);

    tc_gemm<32, A_CONV, E_RES_RELU><<<g(M0), 256, SM32>>>(
        x0a_i, nullptr, nbr0, sym4(w_b0h), sym4(w_b0l), x0a_f, nullptr, x0b_i,
        M0, 32, 864, 896, 32, 27, 0);

    tc_gemm<64, A_CONV, E_RELU><<<g(M1), 256, SM64>>>(
        x0b_i, nullptr, down1, sym4(w_d1h), sym4(w_d1l), nullptr, x1a_f, x1a_i,
        M1, 64, 256, 256, 32, 8, 0);
    tc_gemm<64, A_CONV, E_RES_RELU><<<g(M1), 256, SM64>>>(
        x1a_i, nullptr, nbr1, sym4(w_b1h), sym4(w_b1l), x1a_f, nullptr, x1b_i,
        M1, 64, 1728, 1728, 64, 27, 0);

    tc_gemm<128, A_CONV, E_RELU><<<g(M2), 256, SM128>>>(
        x1b_i, nullptr, down2, sym4(w_d2h), sym4(w_d2l), nullptr, x2a_f, x2a_i,
        M2, 128, 512, 512, 64, 8, 0);
    tc_gemm<128, A_CONV, E_RES_RELU><<<g(M2), 256, SM128>>>(
        x2a_i, nullptr, nbr2, sym4(w_b2h), sym4(w_b2l), x2a_f, nullptr, x2b_i,
        M2, 128, 3456, 3456, 128, 27, 0);

    tc_gemm<256, A_CONV, E_RELU><<<g(M3), 256, SM256>>>(
        x2b_i, nullptr, down3, sym4(w_d3h), sym4(w_d3l), nullptr, x3a_f, x3a_i,
        M3, 256, 1024, 1024, 128, 8, 0);
    tc_gemm<256, A_CONV, E_RES_RELU><<<g(M3), 256, SM256>>>(
        x3a_i, nullptr, nbr3, sym4(w_b3h), sym4(w_b3l), x3a_f, nullptr, x3b_i,
        M3, 256, 6912, 6912, 256, 27, 0);

    // ---- decoder ----
    tc_gemm<256, A_CONCAT, E_RELU><<<g(M2), 256, SM256>>>(
        x3b_i, x2b_i, up2, sym4(w_u2h), sym4(w_u2l), nullptr, nullptr, u2_i,
        M2, 256, 384, 384, 0, 0, 256);
    tc_gemm<128, A_CONCAT, E_RELU><<<g(M1), 256, SM128>>>(
        u2_i, x1b_i, up1, sym4(w_u1h), sym4(w_u1l), nullptr, nullptr, u1_i,
        M1, 128, 320, 320, 0, 0, 256);
    tc_gemm<128, A_CONCAT, E_RELU><<<g(M0), 256, SM128>>>(
        u1_i, x0b_i, up0, sym4(w_u0h), sym4(w_u0l), nullptr, u0_f, nullptr,
        M0, 96, 160, 192, 0, 0, 128);

    // ---- final: gather 8192 seed rows, project to 512, transpose-store ----
    gemm_final<128, 128, 16, 8, 8><<<dim3(64, 4), 256>>>(
        u0_f, seed_idx, W_out, out, 8 * 1024, 512, 96);
}

// round 11
// speedup vs baseline: 1.4369x; 1.4369x over previous
#include <cuda_runtime.h>
#include <cuda_bf16.h>
#include <cstdint>

// ---------------------------------------------------------------------------
// MinkUNet backbone, round 9 (re-run of R7 after infra failure):
// tcgen05 bf16 double-double implicit GEMM with fully asynchronous tile fill.
// A (gathered) and B (weights) move to smem via cp.async.cg 16B copies;
// neighbor indices prefetched one K-tile ahead; features stored interleaved
// bf16 hi/lo so gathers are raw byte copies. OOB cp.async sources clamped to
// a valid address (size-0 copies still carry translatable pointers).
// ---------------------------------------------------------------------------

#define KN0 100000
#define KN1 50000
#define KN2 25000
#define KN3 12500

// fp32 scratch (only where consumed as fp32)
__device__ float g_x0a_f[KN0 * 32];
__device__ float g_x1a_f[KN1 * 64];
__device__ float g_x2a_f[KN2 * 128];
__device__ float g_x3a_f[KN3 * 256];
__device__ float g_u0_f[KN0 * 96];

// interleaved bf16 hi/lo scratch (16B hi chunk + 16B lo chunk per 8 elems)
__device__ uint4 g_x0a_i[KN0 * 32 / 4];
__device__ uint4 g_x0b_i[KN0 * 32 / 4];
__device__ uint4 g_x1a_i[KN1 * 64 / 4];
__device__ uint4 g_x1b_i[KN1 * 64 / 4];
__device__ uint4 g_x2a_i[KN2 * 128 / 4];
__device__ uint4 g_x2b_i[KN2 * 128 / 4];
__device__ uint4 g_x3a_i[KN3 * 256 / 4];
__device__ uint4 g_x3b_i[KN3 * 256 / 4];
__device__ uint4 g_u2_i[KN2 * 256 / 4];
__device__ uint4 g_u1_i[KN1 * 128 / 4];

#define WDECL(name, npad, kpad) \
    __device__ uint4 name##h[(npad) * (kpad) / 8]; \
    __device__ uint4 name##l[(npad) * (kpad) / 8];
WDECL(w_b0, 32, 896)
WDECL(w_d1, 64, 256)
WDECL(w_b1, 64, 1728)
WDECL(w_d2, 128, 512)
WDECL(w_b2, 128, 3456)
WDECL(w_d3, 256, 1024)
WDECL(w_b3, 256, 6912)
WDECL(w_u2, 256, 384)
WDECL(w_u1, 128, 320)
WDECL(w_u0, 128, 192)

#define A_CONV 0
#define A_CONCAT 1
#define E_RELU 0
#define E_RES_RELU 1

#if defined(__CUDA_ARCH__) && !defined(__CUDA_ARCH_FEAT_SM103_ALL)
#define NO_TC 1
#endif

// ---------------- PTX helpers ----------------
__device__ __forceinline__ uint32_t smem_u32(const void* p) {
    uint32_t a;
    asm("{ .reg .u64 t; cvta.to.shared.u64 t, %1; cvt.u32.u64 %0, t; }" : "=r"(a) : "l"(p));
    return a;
}
__device__ __forceinline__ uint32_t elect_one() {
    uint32_t p;
    asm volatile("{ .reg .pred p; elect.sync _|p, 0xFFFFFFFF; selp.b32 %0, 1, 0, p; }" : "=r"(p));
    return p;
}
#define MBAR_INIT(a, c) asm volatile("mbarrier.init.shared.b64 [%0], %1;" :: "r"(a), "r"(c) : "memory")
#define MBAR_INVAL(a)   asm volatile("mbarrier.inval.shared.b64 [%0];" :: "r"(a) : "memory")
#define MBAR_WAIT(a, ph) do { \
    uint32_t _m = (a), _p = (ph), _d; \
    asm volatile("{ .reg .pred p; mbarrier.try_wait.parity.acquire.cta.shared::cta.b64 p, [%1], %2; selp.b32 %0,1,0,p; }" \
                 : "=r"(_d) : "r"(_m), "r"(_p) : "memory"); \
    if (!_d) { \
        asm volatile("{ .reg .pred P1; WL_%=: mbarrier.try_wait.parity.acquire.cta.shared::cta.b64 P1, [%0], %1, 0x989680; @P1 bra.uni WD_%=; bra.uni WL_%=; WD_%=: }" \
                     :: "r"(_m), "r"(_p) : "memory"); \
    } } while (0)
#define FENCE_ASYNC() asm volatile("fence.proxy.async.shared::cta;" ::: "memory")

// cp.async 16B, variable src-size (0 => zero-fill)
#define CP_ASYNC16(dst, src, sz) \
    asm volatile("cp.async.cg.shared.global [%0], [%1], 16, %2;" \
                 :: "r"(dst), "l"(__cvta_generic_to_global(src)), "r"(sz) : "memory")
#define CP_COMMIT() asm volatile("cp.async.commit_group;" ::: "memory")
#define CP_WAIT0()  asm volatile("cp.async.wait_group 0;" ::: "memory")

#ifdef NO_TC
#define TC_ALLOC(sa, n)   ((void)0)
#define TC_DEALLOC(t, n)  ((void)0)
#define TC_RELINQ()       ((void)0)
#define TC_COMMIT(a)      ((void)0)
#define TC_FENCE_AFTER()  ((void)0)
#define TC_FENCE_BEFORE() ((void)0)
#define TC_WAIT_LD()      ((void)0)
#define TC_LD_X32(r, ta)  do { _Pragma("unroll") for (int _i = 0; _i < 32; ++_i) (r)[_i] = 0u; } while (0)
__device__ __forceinline__ void mma_bf16_ss(uint32_t, uint64_t, uint64_t, uint32_t, uint32_t) {}
#else
#define TC_ALLOC(sa, n)   asm volatile("tcgen05.alloc.cta_group::1.sync.aligned.shared::cta.b32 [%0], %1;" :: "r"(sa), "r"(n) : "memory")
#define TC_DEALLOC(t, n)  asm volatile("tcgen05.dealloc.cta_group::1.sync.aligned.b32 %0, %1;" :: "r"(t), "r"(n))
#define TC_RELINQ()       asm volatile("tcgen05.relinquish_alloc_permit.cta_group::1.sync.aligned;")
#define TC_COMMIT(a)      asm volatile("tcgen05.commit.cta_group::1.mbarrier::arrive::one.shared::cluster.b64 [%0];" :: "r"(a) : "memory")
#define TC_FENCE_AFTER()  asm volatile("tcgen05.fence::after_thread_sync;" ::: "memory")
#define TC_FENCE_BEFORE() asm volatile("tcgen05.fence::before_thread_sync;" ::: "memory")
#define TC_WAIT_LD()      asm volatile("tcgen05.wait::ld.sync.aligned;" ::: "memory")
#define TC_LD_X32(r, ta) \
    asm volatile("tcgen05.ld.sync.aligned.32x32b.x32.b32 {%0,%1,%2,%3,%4,%5,%6,%7,%8,%9,%10,%11,%12,%13,%14,%15,%16,%17,%18,%19,%20,%21,%22,%23,%24,%25,%26,%27,%28,%29,%30,%31}, [%32];" \
        : "=r"((r)[0]), "=r"((r)[1]), "=r"((r)[2]), "=r"((r)[3]), "=r"((r)[4]), "=r"((r)[5]), "=r"((r)[6]), "=r"((r)[7]), \
          "=r"((r)[8]), "=r"((r)[9]), "=r"((r)[10]), "=r"((r)[11]), "=r"((r)[12]), "=r"((r)[13]), "=r"((r)[14]), "=r"((r)[15]), \
          "=r"((r)[16]), "=r"((r)[17]), "=r"((r)[18]), "=r"((r)[19]), "=r"((r)[20]), "=r"((r)[21]), "=r"((r)[22]), "=r"((r)[23]), \
          "=r"((r)[24]), "=r"((r)[25]), "=r"((r)[26]), "=r"((r)[27]), "=r"((r)[28]), "=r"((r)[29]), "=r"((r)[30]), "=r"((r)[31]) \
        : "r"(ta))
__device__ __forceinline__ void mma_bf16_ss(uint32_t d, uint64_t ad, uint64_t bd,
                                            uint32_t idesc, uint32_t acc) {
    asm volatile(
        "{ .reg .pred p; setp.ne.u32 p, %5, 0;\n\t"
        "tcgen05.mma.cta_group::1.kind::f16 [%0], %1, %2, %3, {%4,%4,%4,%4}, p; }"
        :: "r"(d), "l"(ad), "l"(bd), "r"(idesc), "r"(0u), "r"(acc) : "memory");
}
#endif

// SW128 K-major descriptor: layout=2, version=1, SBO=64, LBO=1
__device__ __forceinline__ uint64_t mk_desc(uint32_t addr) {
    const uint64_t base = (uint64_t(2) << 61) | (uint64_t(1) << 46) |
                          (uint64_t(64) << 32) | (uint64_t(1) << 16);
    return base | ((uint64_t)(addr >> 4) & 0x3FFF);
}
__device__ __forceinline__ uint32_t sw128(uint32_t off) {
    return off ^ ((off >> 3) & 0x70);
}
// split 2 floats into packed hi/lo bf16x2 (memory order x0 then x1)
__device__ __forceinline__ void split2(float x0, float x1, uint32_t& h, uint32_t& l) {
    uint32_t hp;
    asm("cvt.rn.satfinite.bf16x2.f32 %0, %1, %2;" : "=r"(hp) : "f"(x1), "f"(x0));
    float h0 = __uint_as_float(hp << 16);
    float h1 = __uint_as_float(hp & 0xFFFF0000u);
    float l0 = x0 - h0, l1 = x1 - h1;
    uint32_t lp;
    asm("cvt.rn.satfinite.bf16x2.f32 %0, %1, %2;" : "=r"(lp) : "f"(l1), "f"(l0));
    h = hp; l = lp;
}

// ---------------- tensor-core gather GEMM ----------------
// Tile: M=128 x N=NT, BK=64 elems (128B bf16 rows), 2-stage cp.async pipeline.
template <int NT, int AMODE, int EPI>
__global__ __launch_bounds__(256, 1) void tc_gemm(
    const uint4* __restrict__ fAi, const uint4* __restrict__ fBi,
    const int* __restrict__ idx,
    const uint4* __restrict__ Wh, const uint4* __restrict__ Wl,
    const float* __restrict__ res, float* __restrict__ out,
    uint4* __restrict__ outI,
    int M, int Cout, int Kdim, int Kpad, int Cin, int KN, int Ca)
{
    constexpr int AB = 128 * 128;          // bytes per A subtile (hi or lo)
    constexpr int BB = NT * 128;           // bytes per B subtile (hi or lo)
    constexpr int STAGE = 2 * AB + 2 * BB;
    constexpr uint32_t IDESC =
        (1u << 4) | (1u << 7) | (1u << 10) | ((NT / 8) << 17) | (8u << 24);

    extern __shared__ char dsm[];
    __shared__ uint32_t s_tmem[1];
    __shared__ __align__(16) unsigned long long s_mbar[2];

    const int tid = threadIdx.x;
    const int wid = tid >> 5;
    const int lid = tid & 31;

    const uint32_t raw = smem_u32(dsm);
    const uint32_t sb = (raw + 1023u) & ~1023u;   // 1024B-aligned tile base

    const uint32_t mb0 = smem_u32(&s_mbar[0]);
    const uint32_t mb1 = mb0 + 8;
    const uint32_t tptr = smem_u32(&s_tmem[0]);

    if (wid == 0) TC_ALLOC(tptr, 256);
    if (tid == 0) { MBAR_INIT(mb0, 1); MBAR_INIT(mb1, 1); }
    __syncthreads();
    const uint32_t tmem = s_tmem[0];

    const int m0 = blockIdx.x * 128;
    const int ntile = Kpad / 64;
    const int ar = tid >> 1;              // A row 0..127
    const int ac0 = (tid & 1) * 4;        // first of 4 chunks (16B hi + 16B lo each)
    const int m = m0 + ar;
    const bool mok = (m < M);
    const int mc = mok ? m : 0;

    const uint64_t dAh0 = mk_desc(sb);
    const uint64_t dAl0 = mk_desc(sb + AB);
    const uint64_t dBh0 = mk_desc(sb + 2 * AB);
    const uint64_t dBl0 = mk_desc(sb + 2 * AB + BB);

    // fixed gather index for concat layers
    int g_fixed = 0;
    if (AMODE == A_CONCAT && mok) g_fixed = idx[m];
    // prefetched conv index (one per thread per K-tile: the 32-elem half of a
    // 64-aligned K-tile always lies inside one kernel offset since Cin >= 32)
    int g_cur = 0;
    if (AMODE == A_CONV && mok) g_cur = idx[(size_t)m * KN + (ac0 * 8) / Cin];

    int use0 = 0, use1 = 0;

    for (int t = 0; t < ntile; ++t) {
        const int b = t & 1;
        const uint32_t mb = b ? mb1 : mb0;
        const int use = b ? use1 : use0;
        if (use > 0) MBAR_WAIT(mb, (use - 1) & 1);

        const uint32_t AhS = sb + b * STAGE;
        const uint32_t AlS = AhS + AB;
        const uint32_t BhS = AhS + 2 * AB;
        const uint32_t BlS = BhS + BB;
        const int kt = t * 64;

        // prefetch next tile's gather index (breaks idx->data dependence)
        int g_next = 0;
        if (AMODE == A_CONV && mok && (t + 1) < ntile)
            g_next = idx[(size_t)m * KN + ((t + 1) * 64 + ac0 * 8) / Cin];

        // ---- A: 4 chunks of (16B hi + 16B lo) via cp.async ----
#pragma unroll
        for (int c = ac0; c < ac0 + 4; ++c) {
            const int kk = kt + c * 8;
            const uint32_t sw = sw128((uint32_t)(ar * 128 + c * 16));
            const bool ok = (mok && kk < Kdim);
            const uint32_t sz = ok ? 16u : 0u;
            const uint4* src;
            if (AMODE == A_CONV) {
                const int kOff = kk / Cin;
                const int ci = kk - kOff * Cin;
                const size_t off = ok ? (((size_t)g_cur * Cin + ci) >> 3) : 0;
                src = fAi + 2 * off;
            } else {
                if (kk < Ca) {
                    src = fAi + 2 * (((size_t)g_fixed * Ca + kk) >> 3);
                } else {
                    const size_t off = ok ? (((size_t)mc * (Kdim - Ca) + (kk - Ca)) >> 3) : 0;
                    src = fBi + 2 * off;
                }
            }
            CP_ASYNC16(AhS + sw, src, sz);
            CP_ASYNC16(AlS + sw, src + 1, sz);
        }
        // ---- B via cp.async (padded: unconditional) ----
        const int kq = kt / 8;
        const int kpq = Kpad / 8;
        for (int i = tid; i < NT * 8; i += 256) {
            const int n = i >> 3, j = i & 7;
            const uint32_t sw = sw128((uint32_t)(n * 128 + j * 16));
            const uint4* wsrc_h = Wh + (size_t)n * kpq + kq + j;
            const uint4* wsrc_l = Wl + (size_t)n * kpq + kq + j;
            CP_ASYNC16(BhS + sw, wsrc_h, 16u);
            CP_ASYNC16(BlS + sw, wsrc_l, 16u);
        }
        CP_COMMIT();
        CP_WAIT0();
        FENCE_ASYNC();
        __syncthreads();

        // ---- issue MMAs ----
        if (wid == 0 && elect_one()) {
            const uint64_t so = (uint64_t)b * (STAGE >> 4);
#pragma unroll
            for (int ks = 0; ks < 4; ++ks) {
                const uint64_t o = so + ks * 2;
                mma_bf16_ss(tmem, dAh0 + o, dBh0 + o, IDESC, !(t == 0 && ks == 0));
                mma_bf16_ss(tmem, dAh0 + o, dBl0 + o, IDESC, 1u);
                mma_bf16_ss(tmem, dAl0 + o, dBh0 + o, IDESC, 1u);
            }
            TC_COMMIT(mb);
        }
        if (b) use1++; else use0++;
        g_cur = g_next;
    }
    if (use0 > 0) MBAR_WAIT(mb0, (use0 - 1) & 1);
    if (use1 > 0) MBAR_WAIT(mb1, (use1 - 1) & 1);
    TC_FENCE_AFTER();

    // ---- epilogue: both warpgroups read TMEM (subpartition = wid&3) ----
    const int sub = wid & 3;
    const int half = wid >> 2;
    const int mr = m0 + sub * 32 + lid;
    constexpr int CH = NT / 32;
    for (int c = half; c < CH; c += 2) {
        uint32_t r[32];
        TC_LD_X32(r, tmem + c * 32 + ((uint32_t)sub << 21));
        TC_WAIT_LD();
        const int nb = c * 32;
        if (mr < M && nb < Cout) {
#pragma unroll
            for (int j = 0; j < 32; j += 8) {
                float v[8];
#pragma unroll
                for (int q = 0; q < 8; ++q)
                    v[q] = fmaxf(__uint_as_float(r[j + q]), 0.f);
                if (EPI == E_RES_RELU) {
                    const float4 r0 = *reinterpret_cast<const float4*>(
                        res + (size_t)mr * Cout + nb + j);
                    const float4 r1 = *reinterpret_cast<const float4*>(
                        res + (size_t)mr * Cout + nb + j + 4);
                    v[0] += r0.x; v[1] += r0.y; v[2] += r0.z; v[3] += r0.w;
                    v[4] += r1.x; v[5] += r1.y; v[6] += r1.z; v[7] += r1.w;
                }
                if (out) {
                    float4 o0 = make_float4(v[0], v[1], v[2], v[3]);
                    float4 o1 = make_float4(v[4], v[5], v[6], v[7]);
                    *reinterpret_cast<float4*>(out + (size_t)mr * Cout + nb + j) = o0;
                    *reinterpret_cast<float4*>(out + (size_t)mr * Cout + nb + j + 4) = o1;
                }
                if (outI) {
                    uint4 hv, lv;
                    split2(v[0], v[1], hv.x, lv.x);
                    split2(v[2], v[3], hv.y, lv.y);
                    split2(v[4], v[5], hv.z, lv.z);
                    split2(v[6], v[7], hv.w, lv.w);
                    const size_t goff = ((size_t)mr * Cout + nb + j) >> 3;
                    outI[2 * goff] = hv;
                    outI[2 * goff + 1] = lv;
                }
            }
        }
    }
    TC_FENCE_BEFORE();
    __syncthreads();
    if (tid == 0) { MBAR_INVAL(mb0); MBAR_INVAL(mb1); }
    __syncthreads();
    if (wid == 0) { TC_RELINQ(); TC_DEALLOC(tmem, 256); }
}

// ---------------- weight conversion: W[K][Cout] fp32 -> [Npad][Kpad] bf16 hi/lo
__global__ void conv_w(const float* __restrict__ W, uint4* __restrict__ Wh,
                       uint4* __restrict__ Wl, int Kdim, int Cout, int Kpad, int Npad)
{
    const int i = blockIdx.x * 256 + threadIdx.x;
    const int total = Npad * Kpad;
    if (i >= total) return;
    const int n = i / Kpad, k = i - n * Kpad;
    float x = 0.f;
    if (n < Cout && k < Kdim) x = W[(size_t)k * Cout + n];
    const __nv_bfloat16 h = __float2bfloat16_rn(x);
    const float hf = __bfloat162float(h);
    const __nv_bfloat16 l = __float2bfloat16_rn(x - hf);
    reinterpret_cast<__nv_bfloat16*>(Wh)[i] = h;
    reinterpret_cast<__nv_bfloat16*>(Wl)[i] = l;
}

// ---------------- SIMT GEMM for the final seed projection ----------------
template <int BM, int BN, int BK, int TM, int TN>
__global__ __launch_bounds__((BM / TM) * (BN / TN), 2) void gemm_final(
    const float* __restrict__ fA, const int* __restrict__ idx,
    const float* __restrict__ W, float* __restrict__ out,
    int M, int Cout, int Kdim)
{
    constexpr int THREADS = (BM / TM) * (BN / TN);
    constexpr int BMP = BM + 4;
    constexpr int A4 = BM * BK / 4;
    constexpr int B4 = BK * BN / 4;
    constexpr int NA = (A4 + THREADS - 1) / THREADS;
    constexpr int NB = (B4 + THREADS - 1) / THREADS;
    constexpr int BK4 = BK / 4;
    constexpr int BN4 = BN / 4;

    __shared__ __align__(16) float As[2][BK][BMP];
    __shared__ __align__(16) float Bs[2][BK][BN];

    const int tid = threadIdx.x;
    const int m0 = blockIdx.x * BM;
    const int n0 = blockIdx.y * BN;
    const int tx = tid % (BN / TN);
    const int ty = tid / (BN / TN);

    float4 ra[NA], rb[NB];
    float acc[TM][TN] = {};
    const int ntile = Kdim / BK;

    auto load_tile = [&](int it) {
        const int kt = it * BK;
#pragma unroll
        for (int t = 0; t < NA; ++t) {
            const int i4 = tid + t * THREADS;
            if (i4 < A4) {
                const int row = i4 / BK4;
                const int c4 = (i4 - row * BK4) * 4;
                const int m = m0 + row;
                float4 v = make_float4(0.f, 0.f, 0.f, 0.f);
                if (m < M) {
                    const int g = idx[m];
                    v = *reinterpret_cast<const float4*>(fA + (size_t)g * Kdim + kt + c4);
                }
                ra[t] = v;
            }
        }
#pragma unroll
        for (int t = 0; t < NB; ++t) {
            const int i4 = tid + t * THREADS;
            if (i4 < B4) {
                const int row = i4 / BN4;
                const int c = (i4 - row * BN4) * 4;
                rb[t] = *reinterpret_cast<const float4*>(W + (size_t)(kt + row) * Cout + n0 + c);
            }
        }
    };
    auto store_tile = [&](int buf) {
#pragma unroll
        for (int t = 0; t < NA; ++t) {
            const int i4 = tid + t * THREADS;
            if (i4 < A4) {
                const int row = i4 / BK4;
                const int c4 = (i4 - row * BK4) * 4;
                As[buf][c4 + 0][row] = ra[t].x;
                As[buf][c4 + 1][row] = ra[t].y;
                As[buf][c4 + 2][row] = ra[t].z;
                As[buf][c4 + 3][row] = ra[t].w;
            }
        }
#pragma unroll
        for (int t = 0; t < NB; ++t) {
            const int i4 = tid + t * THREADS;
            if (i4 < B4) {
                const int row = i4 / BN4;
                const int c = (i4 - row * BN4) * 4;
                *reinterpret_cast<float4*>(&Bs[buf][row][c]) = rb[t];
            }
        }
    };

    load_tile(0); store_tile(0); __syncthreads();
    int buf = 0;
    for (int it = 0; it < ntile; ++it) {
        if (it + 1 < ntile) load_tile(it + 1);
#pragma unroll
        for (int kk = 0; kk < BK; ++kk) {
            float a[TM], b[TN];
#pragma unroll
            for (int i = 0; i < TM; i += 4) {
                const float4 v = *reinterpret_cast<const float4*>(&As[buf][kk][ty * TM + i]);
                a[i] = v.x; a[i + 1] = v.y; a[i + 2] = v.z; a[i + 3] = v.w;
            }
#pragma unroll
            for (int j = 0; j < TN; j += 4) {
                const float4 v = *reinterpret_cast<const float4*>(&Bs[buf][kk][tx * TN + j]);
                b[j] = v.x; b[j + 1] = v.y; b[j + 2] = v.z; b[j + 3] = v.w;
            }
#pragma unroll
            for (int i = 0; i < TM; ++i)
#pragma unroll
                for (int j = 0; j < TN; ++j)
                    acc[i][j] = fmaf(a[i], b[j], acc[i][j]);
        }
        if (it + 1 < ntile) store_tile(buf ^ 1);
        __syncthreads();
        buf ^= 1;
    }
#pragma unroll
    for (int i = 0; i < TM; ++i) {
        const int mm = m0 + ty * TM + i;
        if (mm >= M) continue;
        const int bb = mm >> 10, ss = mm & 1023;
#pragma unroll
        for (int j = 0; j < TN; ++j) {
            const int n = n0 + tx * TN + j;
            out[((size_t)bb * Cout + n) * 1024 + ss] = acc[i][j];
        }
    }
}

// Stem: Cin=3 -> dedicated SIMT kernel; writes fp32 + interleaved bf16.
__global__ __launch_bounds__(256) void stem_k(
    const float* __restrict__ feats, const int* __restrict__ nbr,
    const float* __restrict__ W, float* __restrict__ out,
    uint4* __restrict__ outI, int M)
{
    __shared__ float sW[27 * 3 * 32];
    __shared__ float sg[8][81];
    __shared__ int   sidx[8][27];
    const int tid = threadIdx.x;
    const int m0 = blockIdx.x * 8;

    for (int i = tid; i < 27 * 96; i += 256) sW[i] = W[i];
    for (int i = tid; i < 8 * 27; i += 256) {
        const int r = i / 27, k = i % 27;
        const int m = m0 + r;
        sidx[r][k] = (m < M) ? nbr[(size_t)m * 27 + k] : 0;
    }
    __syncthreads();
    for (int i = tid; i < 8 * 81; i += 256) {
        const int r = i / 81, j = i % 81;
        sg[r][j] = feats[(size_t)sidx[r][j / 3] * 3 + (j % 3)];
    }
    __syncthreads();
    const int r = tid >> 5, co = tid & 31;
    const int m = m0 + r;
    float acc = 0.f;
#pragma unroll
    for (int j = 0; j < 81; ++j)
        acc = fmaf(sg[r][j], sW[j * 32 + co], acc);
    if (m < M) {
        const float v = fmaxf(acc, 0.f);
        out[(size_t)m * 32 + co] = v;
        const __nv_bfloat16 h = __float2bfloat16_rn(v);
        const __nv_bfloat16 l = __float2bfloat16_rn(v - __bfloat162float(h));
        __nv_bfloat16* bi = reinterpret_cast<__nv_bfloat16*>(outI);
        const size_t goff = ((size_t)m * 32 + co) >> 3;
        const int w = co & 7;
        bi[goff * 16 + w] = h;
        bi[goff * 16 + 8 + w] = l;
    }
}

static float* symf(const void* s) { void* p = nullptr; cudaGetSymbolAddress(&p, s); return (float*)p; }
static uint4* sym4(const void* s) { void* p = nullptr; cudaGetSymbolAddress(&p, s); return (uint4*)p; }

extern "C" void kernel_launch(void* const* d_in, const int* in_sizes, int n_in,
                              void* d_out, int out_size)
{
    const float* feats  = (const float*)d_in[0];
    const int* nbr0     = (const int*)d_in[1];
    const int* nbr1     = (const int*)d_in[2];
    const int* nbr2     = (const int*)d_in[3];
    const int* nbr3     = (const int*)d_in[4];
    const int* down1    = (const int*)d_in[5];
    const int* down2    = (const int*)d_in[6];
    const int* down3    = (const int*)d_in[7];
    const int* up2      = (const int*)d_in[8];
    const int* up1      = (const int*)d_in[9];
    const int* up0      = (const int*)d_in[10];
    const int* seed_idx = (const int*)d_in[11];
    const float* W_stem = (const float*)d_in[12];
    const float* W_b0   = (const float*)d_in[13];
    const float* W_d1   = (const float*)d_in[14];
    const float* W_b1   = (const float*)d_in[15];
    const float* W_d2   = (const float*)d_in[16];
    const float* W_b2   = (const float*)d_in[17];
    const float* W_d3   = (const float*)d_in[18];
    const float* W_b3   = (const float*)d_in[19];
    const float* W_u2   = (const float*)d_in[20];
    const float* W_u1   = (const float*)d_in[21];
    const float* W_u0   = (const float*)d_in[22];
    const float* W_out  = (const float*)d_in[23];
    float* out = (float*)d_out;

    float* x0a_f = symf(g_x0a_f); float* x1a_f = symf(g_x1a_f);
    float* x2a_f = symf(g_x2a_f); float* x3a_f = symf(g_x3a_f);
    float* u0_f  = symf(g_u0_f);
    uint4* x0a_i = sym4(g_x0a_i); uint4* x0b_i = sym4(g_x0b_i);
    uint4* x1a_i = sym4(g_x1a_i); uint4* x1b_i = sym4(g_x1b_i);
    uint4* x2a_i = sym4(g_x2a_i); uint4* x2b_i = sym4(g_x2b_i);
    uint4* x3a_i = sym4(g_x3a_i); uint4* x3b_i = sym4(g_x3b_i);
    uint4* u2_i  = sym4(g_u2_i);  uint4* u1_i  = sym4(g_u1_i);

    const int SM32  = (2 * 128 * 128 + 2 * 32 * 128) * 2 + 1024;
    const int SM64  = (2 * 128 * 128 + 2 * 64 * 128) * 2 + 1024;
    const int SM128 = (2 * 128 * 128 + 2 * 128 * 128) * 2 + 1024;
    const int SM256 = (2 * 128 * 128 + 2 * 256 * 128) * 2 + 1024;
    cudaFuncSetAttribute(tc_gemm<32,  A_CONV,   E_RES_RELU>, cudaFuncAttributeMaxDynamicSharedMemorySize, SM32);
    cudaFuncSetAttribute(tc_gemm<64,  A_CONV,   E_RELU>,     cudaFuncAttributeMaxDynamicSharedMemorySize, SM64);
    cudaFuncSetAttribute(tc_gemm<64,  A_CONV,   E_RES_RELU>, cudaFuncAttributeMaxDynamicSharedMemorySize, SM64);
    cudaFuncSetAttribute(tc_gemm<128, A_CONV,   E_RELU>,     cudaFuncAttributeMaxDynamicSharedMemorySize, SM128);
    cudaFuncSetAttribute(tc_gemm<128, A_CONV,   E_RES_RELU>, cudaFuncAttributeMaxDynamicSharedMemorySize, SM128);
    cudaFuncSetAttribute(tc_gemm<128, A_CONCAT, E_RELU>,     cudaFuncAttributeMaxDynamicSharedMemorySize, SM128);
    cudaFuncSetAttribute(tc_gemm<256, A_CONV,   E_RELU>,     cudaFuncAttributeMaxDynamicSharedMemorySize, SM256);
    cudaFuncSetAttribute(tc_gemm<256, A_CONV,   E_RES_RELU>, cudaFuncAttributeMaxDynamicSharedMemorySize, SM256);
    cudaFuncSetAttribute(tc_gemm<256, A_CONCAT, E_RELU>,     cudaFuncAttributeMaxDynamicSharedMemorySize, SM256);

    auto cw = [&](const float* W, uint4* Wh, uint4* Wl, int Kd, int Co, int Kp, int Np) {
        const int total = Np * Kp;
        conv_w<<<(total + 255) / 256, 256>>>(W, Wh, Wl, Kd, Co, Kp, Np);
    };
    cw(W_b0, sym4(w_b0h), sym4(w_b0l),  864,  32,  896,  32);
    cw(W_d1, sym4(w_d1h), sym4(w_d1l),  256,  64,  256,  64);
    cw(W_b1, sym4(w_b1h), sym4(w_b1l), 1728,  64, 1728,  64);
    cw(W_d2, sym4(w_d2h), sym4(w_d2l),  512, 128,  512, 128);
    cw(W_b2, sym4(w_b2h), sym4(w_b2l), 3456, 128, 3456, 128);
    cw(W_d3, sym4(w_d3h), sym4(w_d3l), 1024, 256, 1024, 256);
    cw(W_b3, sym4(w_b3h), sym4(w_b3l), 6912, 256, 6912, 256);
    cw(W_u2, sym4(w_u2h), sym4(w_u2l),  384, 256,  384, 256);
    cw(W_u1, sym4(w_u1h), sym4(w_u1l),  320, 128,  320, 128);
    cw(W_u0, sym4(w_u0h), sym4(w_u0l),  160,  96,  192, 128);

    const int M0 = KN0, M1 = KN1, M2 = KN2, M3 = KN3;
    auto g = [](int M) { return (unsigned)((M + 127) / 128); };

    // ---- encoder ----
    stem_k<<<(M0 + 7) / 8, 256>>>(feats, nbr0, W_stem, x0a_f, x0a_i, M0);

    tc_gemm<32, A_CONV, E_RES_RELU><<<g(M0), 256, SM32>>>(
        x0a_i, nullptr, nbr0, sym4(w_b0h), sym4(w_b0l), x0a_f, nullptr, x0b_i,
        M0, 32, 864, 896, 32, 27, 0);

    tc_gemm<64, A_CONV, E_RELU><<<g(M1), 256, SM64>>>(
        x0b_i, nullptr, down1, sym4(w_d1h), sym4(w_d1l), nullptr, x1a_f, x1a_i,
        M1, 64, 256, 256, 32, 8, 0);
    tc_gemm<64, A_CONV, E_RES_RELU><<<g(M1), 256, SM64>>>(
        x1a_i, nullptr, nbr1, sym4(w_b1h), sym4(w_b1l), x1a_f, nullptr, x1b_i,
        M1, 64, 1728, 1728, 64, 27, 0);

    tc_gemm<128, A_CONV, E_RELU><<<g(M2), 256, SM128>>>(
        x1b_i, nullptr, down2, sym4(w_d2h), sym4(w_d2l), nullptr, x2a_f, x2a_i,
        M2, 128, 512, 512, 64, 8, 0);
    tc_gemm<128, A_CONV, E_RES_RELU><<<g(M2), 256, SM128>>>(
        x2a_i, nullptr, nbr2, sym4(w_b2h), sym4(w_b2l), x2a_f, nullptr, x2b_i,
        M2, 128, 3456, 3456, 128, 27, 0);

    tc_gemm<256, A_CONV, E_RELU><<<g(M3), 256, SM256>>>(
        x2b_i, nullptr, down3, sym4(w_d3h), sym4(w_d3l), nullptr, x3a_f, x3a_i,
        M3, 256, 1024, 1024, 128, 8, 0);
    tc_gemm<256, A_CONV, E_RES_RELU><<<g(M3), 256, SM256>>>(
        x3a_i, nullptr, nbr3, sym4(w_b3h), sym4(w_b3l), x3a_f, nullptr, x3b_i,
        M3, 256, 6912, 6912, 256, 27, 0);

    // ---- decoder ----
    tc_gemm<256, A_CONCAT, E_RELU><<<g(M2), 256, SM256>>>(
        x3b_i, x2b_i, up2, sym4(w_u2h), sym4(w_u2l), nullptr, nullptr, u2_i,
        M2, 256, 384, 384, 0, 0, 256);
    tc_gemm<128, A_CONCAT, E_RELU><<<g(M1), 256, SM128>>>(
        u2_i, x1b_i, up1, sym4(w_u1h), sym4(w_u1l), nullptr, nullptr, u1_i,
        M1, 128, 320, 320, 0, 0, 256);
    tc_gemm<128, A_CONCAT, E_RELU><<<g(M0), 256, SM128>>>(
        u1_i, x0b_i, up0, sym4(w_u0h), sym4(w_u0l), nullptr, u0_f, nullptr,
        M0, 96, 160, 192, 0, 0, 128);

    // ---- final: gather 8192 seed rows, project to 512, transpose-store ----
    gemm_final<128, 128, 16, 8, 8><<<dim3(64, 4), 256>>>(
        u0_f, seed_idx, W_out, out, 8 * 1024, 512, 96);
}

// round 16
// speedup vs baseline: 1.4851x; 1.0335x over previous
#include <cuda_runtime.h>
#include <cuda_bf16.h>
#include <cstdint>

// ---------------------------------------------------------------------------
// MinkUNet backbone, round 12: software-pipelined cp.async fill.
// At iter t: wait buffer-free mbar, issue fill(t+1) (non-blocking),
// cp.async.wait_group 1 (fill(t) — issued an iteration ago, already landed),
// sync, issue MMA(t). Fill latency fully hidden behind MMA of prior tile.
// Neighbor indices prefetched two tiles ahead. Otherwise identical to R11
// (bf16 double-double tcgen05, interleaved hi/lo feature maps).
// ---------------------------------------------------------------------------

#define KN0 100000
#define KN1 50000
#define KN2 25000
#define KN3 12500

__device__ float g_x0a_f[KN0 * 32];
__device__ float g_x1a_f[KN1 * 64];
__device__ float g_x2a_f[KN2 * 128];
__device__ float g_x3a_f[KN3 * 256];
__device__ float g_u0_f[KN0 * 96];

__device__ uint4 g_x0a_i[KN0 * 32 / 4];
__device__ uint4 g_x0b_i[KN0 * 32 / 4];
__device__ uint4 g_x1a_i[KN1 * 64 / 4];
__device__ uint4 g_x1b_i[KN1 * 64 / 4];
__device__ uint4 g_x2a_i[KN2 * 128 / 4];
__device__ uint4 g_x2b_i[KN2 * 128 / 4];
__device__ uint4 g_x3a_i[KN3 * 256 / 4];
__device__ uint4 g_x3b_i[KN3 * 256 / 4];
__device__ uint4 g_u2_i[KN2 * 256 / 4];
__device__ uint4 g_u1_i[KN1 * 128 / 4];

#define WDECL(name, npad, kpad) \
    __device__ uint4 name##h[(npad) * (kpad) / 8]; \
    __device__ uint4 name##l[(npad) * (kpad) / 8];
WDECL(w_b0, 32, 896)
WDECL(w_d1, 64, 256)
WDECL(w_b1, 64, 1728)
WDECL(w_d2, 128, 512)
WDECL(w_b2, 128, 3456)
WDECL(w_d3, 256, 1024)
WDECL(w_b3, 256, 6912)
WDECL(w_u2, 256, 384)
WDECL(w_u1, 128, 320)
WDECL(w_u0, 128, 192)

#define A_CONV 0
#define A_CONCAT 1
#define E_RELU 0
#define E_RES_RELU 1

#if defined(__CUDA_ARCH__) && !defined(__CUDA_ARCH_FEAT_SM103_ALL)
#define NO_TC 1
#endif

// ---------------- PTX helpers ----------------
__device__ __forceinline__ uint32_t smem_u32(const void* p) {
    uint32_t a;
    asm("{ .reg .u64 t; cvta.to.shared.u64 t, %1; cvt.u32.u64 %0, t; }" : "=r"(a) : "l"(p));
    return a;
}
__device__ __forceinline__ uint32_t elect_one() {
    uint32_t p;
    asm volatile("{ .reg .pred p; elect.sync _|p, 0xFFFFFFFF; selp.b32 %0, 1, 0, p; }" : "=r"(p));
    return p;
}
#define MBAR_INIT(a, c) asm volatile("mbarrier.init.shared.b64 [%0], %1;" :: "r"(a), "r"(c) : "memory")
#define MBAR_INVAL(a)   asm volatile("mbarrier.inval.shared.b64 [%0];" :: "r"(a) : "memory")
#define MBAR_WAIT(a, ph) do { \
    uint32_t _m = (a), _p = (ph), _d; \
    asm volatile("{ .reg .pred p; mbarrier.try_wait.parity.acquire.cta.shared::cta.b64 p, [%1], %2; selp.b32 %0,1,0,p; }" \
                 : "=r"(_d) : "r"(_m), "r"(_p) : "memory"); \
    if (!_d) { \
        asm volatile("{ .reg .pred P1; WL_%=: mbarrier.try_wait.parity.acquire.cta.shared::cta.b64 P1, [%0], %1, 0x989680; @P1 bra.uni WD_%=; bra.uni WL_%=; WD_%=: }" \
                     :: "r"(_m), "r"(_p) : "memory"); \
    } } while (0)
#define FENCE_ASYNC() asm volatile("fence.proxy.async.shared::cta;" ::: "memory")

// cp.async 16B, variable src-size (0 => zero-fill)
#define CP_ASYNC16(dst, src, sz) \
    asm volatile("cp.async.cg.shared.global [%0], [%1], 16, %2;" \
                 :: "r"(dst), "l"(__cvta_generic_to_global(src)), "r"(sz) : "memory")
#define CP_COMMIT() asm volatile("cp.async.commit_group;" ::: "memory")
#define CP_WAIT0()  asm volatile("cp.async.wait_group 0;" ::: "memory")
#define CP_WAIT1()  asm volatile("cp.async.wait_group 1;" ::: "memory")

#ifdef NO_TC
#define TC_ALLOC(sa, n)   ((void)0)
#define TC_DEALLOC(t, n)  ((void)0)
#define TC_RELINQ()       ((void)0)
#define TC_COMMIT(a)      ((void)0)
#define TC_FENCE_AFTER()  ((void)0)
#define TC_FENCE_BEFORE() ((void)0)
#define TC_WAIT_LD()      ((void)0)
#define TC_LD_X32(r, ta)  do { _Pragma("unroll") for (int _i = 0; _i < 32; ++_i) (r)[_i] = 0u; } while (0)
__device__ __forceinline__ void mma_bf16_ss(uint32_t, uint64_t, uint64_t, uint32_t, uint32_t) {}
#else
#define TC_ALLOC(sa, n)   asm volatile("tcgen05.alloc.cta_group::1.sync.aligned.shared::cta.b32 [%0], %1;" :: "r"(sa), "r"(n) : "memory")
#define TC_DEALLOC(t, n)  asm volatile("tcgen05.dealloc.cta_group::1.sync.aligned.b32 %0, %1;" :: "r"(t), "r"(n))
#define TC_RELINQ()       asm volatile("tcgen05.relinquish_alloc_permit.cta_group::1.sync.aligned;")
#define TC_COMMIT(a)      asm volatile("tcgen05.commit.cta_group::1.mbarrier::arrive::one.shared::cluster.b64 [%0];" :: "r"(a) : "memory")
#define TC_FENCE_AFTER()  asm volatile("tcgen05.fence::after_thread_sync;" ::: "memory")
#define TC_FENCE_BEFORE() asm volatile("tcgen05.fence::before_thread_sync;" ::: "memory")
#define TC_WAIT_LD()      asm volatile("tcgen05.wait::ld.sync.aligned;" ::: "memory")
#define TC_LD_X32(r, ta) \
    asm volatile("tcgen05.ld.sync.aligned.32x32b.x32.b32 {%0,%1,%2,%3,%4,%5,%6,%7,%8,%9,%10,%11,%12,%13,%14,%15,%16,%17,%18,%19,%20,%21,%22,%23,%24,%25,%26,%27,%28,%29,%30,%31}, [%32];" \
        : "=r"((r)[0]), "=r"((r)[1]), "=r"((r)[2]), "=r"((r)[3]), "=r"((r)[4]), "=r"((r)[5]), "=r"((r)[6]), "=r"((r)[7]), \
          "=r"((r)[8]), "=r"((r)[9]), "=r"((r)[10]), "=r"((r)[11]), "=r"((r)[12]), "=r"((r)[13]), "=r"((r)[14]), "=r"((r)[15]), \
          "=r"((r)[16]), "=r"((r)[17]), "=r"((r)[18]), "=r"((r)[19]), "=r"((r)[20]), "=r"((r)[21]), "=r"((r)[22]), "=r"((r)[23]), \
          "=r"((r)[24]), "=r"((r)[25]), "=r"((r)[26]), "=r"((r)[27]), "=r"((r)[28]), "=r"((r)[29]), "=r"((r)[30]), "=r"((r)[31]) \
        : "r"(ta))
__device__ __forceinline__ void mma_bf16_ss(uint32_t d, uint64_t ad, uint64_t bd,
                                            uint32_t idesc, uint32_t acc) {
    asm volatile(
        "{ .reg .pred p; setp.ne.u32 p, %5, 0;\n\t"
        "tcgen05.mma.cta_group::1.kind::f16 [%0], %1, %2, %3, {%4,%4,%4,%4}, p; }"
        :: "r"(d), "l"(ad), "l"(bd), "r"(idesc), "r"(0u), "r"(acc) : "memory");
}
#endif

// SW128 K-major descriptor: layout=2, version=1, SBO=64, LBO=1
__device__ __forceinline__ uint64_t mk_desc(uint32_t addr) {
    const uint64_t base = (uint64_t(2) << 61) | (uint64_t(1) << 46) |
                          (uint64_t(64) << 32) | (uint64_t(1) << 16);
    return base | ((uint64_t)(addr >> 4) & 0x3FFF);
}
__device__ __forceinline__ uint32_t sw128(uint32_t off) {
    return off ^ ((off >> 3) & 0x70);
}
__device__ __forceinline__ void split2(float x0, float x1, uint32_t& h, uint32_t& l) {
    uint32_t hp;
    asm("cvt.rn.satfinite.bf16x2.f32 %0, %1, %2;" : "=r"(hp) : "f"(x1), "f"(x0));
    float h0 = __uint_as_float(hp << 16);
    float h1 = __uint_as_float(hp & 0xFFFF0000u);
    float l0 = x0 - h0, l1 = x1 - h1;
    uint32_t lp;
    asm("cvt.rn.satfinite.bf16x2.f32 %0, %1, %2;" : "=r"(lp) : "f"(l1), "f"(l0));
    h = hp; l = lp;
}

// ---------------- tensor-core gather GEMM ----------------
template <int NT, int AMODE, int EPI>
__global__ __launch_bounds__(256, 1) void tc_gemm(
    const uint4* __restrict__ fAi, const uint4* __restrict__ fBi,
    const int* __restrict__ idx,
    const uint4* __restrict__ Wh, const uint4* __restrict__ Wl,
    const float* __restrict__ res, float* __restrict__ out,
    uint4* __restrict__ outI,
    int M, int Cout, int Kdim, int Kpad, int Cin, int KN, int Ca)
{
    constexpr int AB = 128 * 128;
    constexpr int BB = NT * 128;
    constexpr int STAGE = 2 * AB + 2 * BB;
    constexpr uint32_t IDESC =
        (1u << 4) | (1u << 7) | (1u << 10) | ((NT / 8) << 17) | (8u << 24);

    extern __shared__ char dsm[];
    __shared__ uint32_t s_tmem[1];
    __shared__ __align__(16) unsigned long long s_mbar[2];

    const int tid = threadIdx.x;
    const int wid = tid >> 5;
    const int lid = tid & 31;

    const uint32_t raw = smem_u32(dsm);
    const uint32_t sb = (raw + 1023u) & ~1023u;

    const uint32_t mb0 = smem_u32(&s_mbar[0]);
    const uint32_t mb1 = mb0 + 8;
    const uint32_t tptr = smem_u32(&s_tmem[0]);

    if (wid == 0) TC_ALLOC(tptr, 256);
    if (tid == 0) { MBAR_INIT(mb0, 1); MBAR_INIT(mb1, 1); }
    __syncthreads();
    const uint32_t tmem = s_tmem[0];

    const int m0 = blockIdx.x * 128;
    const int ntile = Kpad / 64;
    const int ar = tid >> 1;
    const int ac0 = (tid & 1) * 4;
    const int m = m0 + ar;
    const bool mok = (m < M);
    const int mc = mok ? m : 0;

    const uint64_t dAh0 = mk_desc(sb);
    const uint64_t dAl0 = mk_desc(sb + AB);
    const uint64_t dBh0 = mk_desc(sb + 2 * AB);
    const uint64_t dBl0 = mk_desc(sb + 2 * AB + BB);

    int g_fixed = 0;
    if (AMODE == A_CONCAT && mok) g_fixed = idx[m];

    // index loader for tile t (one kernel-offset per thread per tile)
    auto load_idx = [&](int t) -> int {
        if (AMODE == A_CONV && mok && t < ntile)
            return idx[(size_t)m * KN + (t * 64 + ac0 * 8) / Cin];
        return 0;
    };

    // fill tile t into its buffer (t&1) using gather index g
    auto fill_tile = [&](int t, int g) {
        const int b = t & 1;
        const uint32_t AhS = sb + b * STAGE;
        const uint32_t AlS = AhS + AB;
        const uint32_t BhS = AhS + 2 * AB;
        const uint32_t BlS = BhS + BB;
        const int kt = t * 64;
#pragma unroll
        for (int c = ac0; c < ac0 + 4; ++c) {
            const int kk = kt + c * 8;
            const uint32_t sw = sw128((uint32_t)(ar * 128 + c * 16));
            const bool ok = (mok && kk < Kdim);
            const uint32_t sz = ok ? 16u : 0u;
            const uint4* src;
            if (AMODE == A_CONV) {
                const int kOff = kk / Cin;
                const int ci = kk - kOff * Cin;
                const size_t off = ok ? (((size_t)g * Cin + ci) >> 3) : 0;
                src = fAi + 2 * off;
            } else {
                if (kk < Ca) {
                    src = fAi + 2 * (((size_t)g_fixed * Ca + kk) >> 3);
                } else {
                    const size_t off = ok ? (((size_t)mc * (Kdim - Ca) + (kk - Ca)) >> 3) : 0;
                    src = fBi + 2 * off;
                }
            }
            CP_ASYNC16(AhS + sw, src, sz);
            CP_ASYNC16(AlS + sw, src + 1, sz);
        }
        const int kq = kt / 8;
        const int kpq = Kpad / 8;
        for (int i = tid; i < NT * 8; i += 256) {
            const int n = i >> 3, j = i & 7;
            const uint32_t sw = sw128((uint32_t)(n * 128 + j * 16));
            CP_ASYNC16(BhS + sw, Wh + (size_t)n * kpq + kq + j, 16u);
            CP_ASYNC16(BlS + sw, Wl + (size_t)n * kpq + kq + j, 16u);
        }
    };

    int use0 = 0, use1 = 0;

    // prologue: fill tile 0; prefetch index for tile 1
    int g_fill = load_idx(0);
    fill_tile(0, g_fill);
    CP_COMMIT();
    g_fill = load_idx(1);

    for (int t = 0; t < ntile; ++t) {
        const int b = t & 1;
        if (t + 1 < ntile) {
            const int nb_ = b ^ 1;
            const int nuse = nb_ ? use1 : use0;
            if (nuse > 0) MBAR_WAIT(nb_ ? mb1 : mb0, (nuse - 1) & 1);
            fill_tile(t + 1, g_fill);
            CP_COMMIT();
            g_fill = load_idx(t + 2);
            CP_WAIT1();           // fill(t) — issued one iteration ago
        } else {
            CP_WAIT0();
        }
        FENCE_ASYNC();
        __syncthreads();

        if (wid == 0 && elect_one()) {
            const uint64_t so = (uint64_t)b * (STAGE >> 4);
#pragma unroll
            for (int ks = 0; ks < 4; ++ks) {
                const uint64_t o = so + ks * 2;
                mma_bf16_ss(tmem, dAh0 + o, dBh0 + o, IDESC, !(t == 0 && ks == 0));
                mma_bf16_ss(tmem, dAh0 + o, dBl0 + o, IDESC, 1u);
                mma_bf16_ss(tmem, dAl0 + o, dBh0 + o, IDESC, 1u);
            }
            TC_COMMIT(b ? mb1 : mb0);
        }
        if (b) use1++; else use0++;
    }
    if (use0 > 0) MBAR_WAIT(mb0, (use0 - 1) & 1);
    if (use1 > 0) MBAR_WAIT(mb1, (use1 - 1) & 1);
    TC_FENCE_AFTER();

    // ---- epilogue: both warpgroups read TMEM (subpartition = wid&3) ----
    const int sub = wid & 3;
    const int half = wid >> 2;
    const int mr = m0 + sub * 32 + lid;
    constexpr int CH = NT / 32;
    for (int c = half; c < CH; c += 2) {
        uint32_t r[32];
        TC_LD_X32(r, tmem + c * 32 + ((uint32_t)sub << 21));
        TC_WAIT_LD();
        const int nb = c * 32;
        if (mr < M && nb < Cout) {
#pragma unroll
            for (int j = 0; j < 32; j += 8) {
                float v[8];
#pragma unroll
                for (int q = 0; q < 8; ++q)
                    v[q] = fmaxf(__uint_as_float(r[j + q]), 0.f);
                if (EPI == E_RES_RELU) {
                    const float4 r0 = *reinterpret_cast<const float4*>(
                        res + (size_t)mr * Cout + nb + j);
                    const float4 r1 = *reinterpret_cast<const float4*>(
                        res + (size_t)mr * Cout + nb + j + 4);
                    v[0] += r0.x; v[1] += r0.y; v[2] += r0.z; v[3] += r0.w;
                    v[4] += r1.x; v[5] += r1.y; v[6] += r1.z; v[7] += r1.w;
                }
                if (out) {
                    float4 o0 = make_float4(v[0], v[1], v[2], v[3]);
                    float4 o1 = make_float4(v[4], v[5], v[6], v[7]);
                    *reinterpret_cast<float4*>(out + (size_t)mr * Cout + nb + j) = o0;
                    *reinterpret_cast<float4*>(out + (size_t)mr * Cout + nb + j + 4) = o1;
                }
                if (outI) {
                    uint4 hv, lv;
                    split2(v[0], v[1], hv.x, lv.x);
                    split2(v[2], v[3], hv.y, lv.y);
                    split2(v[4], v[5], hv.z, lv.z);
                    split2(v[6], v[7], hv.w, lv.w);
                    const size_t goff = ((size_t)mr * Cout + nb + j) >> 3;
                    outI[2 * goff] = hv;
                    outI[2 * goff + 1] = lv;
                }
            }
        }
    }
    TC_FENCE_BEFORE();
    __syncthreads();
    if (tid == 0) { MBAR_INVAL(mb0); MBAR_INVAL(mb1); }
    __syncthreads();
    if (wid == 0) { TC_RELINQ(); TC_DEALLOC(tmem, 256); }
}

// ---------------- weight conversion ----------------
__global__ void conv_w(const float* __restrict__ W, uint4* __restrict__ Wh,
                       uint4* __restrict__ Wl, int Kdim, int Cout, int Kpad, int Npad)
{
    const int i = blockIdx.x * 256 + threadIdx.x;
    const int total = Npad * Kpad;
    if (i >= total) return;
    const int n = i / Kpad, k = i - n * Kpad;
    float x = 0.f;
    if (n < Cout && k < Kdim) x = W[(size_t)k * Cout + n];
    const __nv_bfloat16 h = __float2bfloat16_rn(x);
    const float hf = __bfloat162float(h);
    const __nv_bfloat16 l = __float2bfloat16_rn(x - hf);
    reinterpret_cast<__nv_bfloat16*>(Wh)[i] = h;
    reinterpret_cast<__nv_bfloat16*>(Wl)[i] = l;
}

// ---------------- SIMT GEMM for the final seed projection ----------------
template <int BM, int BN, int BK, int TM, int TN>
__global__ __launch_bounds__((BM / TM) * (BN / TN), 2) void gemm_final(
    const float* __restrict__ fA, const int* __restrict__ idx,
    const float* __restrict__ W, float* __restrict__ out,
    int M, int Cout, int Kdim)
{
    constexpr int THREADS = (BM / TM) * (BN / TN);
    constexpr int BMP = BM + 4;
    constexpr int A4 = BM * BK / 4;
    constexpr int B4 = BK * BN / 4;
    constexpr int NA = (A4 + THREADS - 1) / THREADS;
    constexpr int NB = (B4 + THREADS - 1) / THREADS;
    constexpr int BK4 = BK / 4;
    constexpr int BN4 = BN / 4;

    __shared__ __align__(16) float As[2][BK][BMP];
    __shared__ __align__(16) float Bs[2][BK][BN];

    const int tid = threadIdx.x;
    const int m0 = blockIdx.x * BM;
    const int n0 = blockIdx.y * BN;
    const int tx = tid % (BN / TN);
    const int ty = tid / (BN / TN);

    float4 ra[NA], rb[NB];
    float acc[TM][TN] = {};
    const int ntile = Kdim / BK;

    auto load_tile = [&](int it) {
        const int kt = it * BK;
#pragma unroll
        for (int t = 0; t < NA; ++t) {
            const int i4 = tid + t * THREADS;
            if (i4 < A4) {
                const int row = i4 / BK4;
                const int c4 = (i4 - row * BK4) * 4;
                const int m = m0 + row;
                float4 v = make_float4(0.f, 0.f, 0.f, 0.f);
                if (m < M) {
                    const int g = idx[m];
                    v = *reinterpret_cast<const float4*>(fA + (size_t)g * Kdim + kt + c4);
                }
                ra[t] = v;
            }
        }
#pragma unroll
        for (int t = 0; t < NB; ++t) {
            const int i4 = tid + t * THREADS;
            if (i4 < B4) {
                const int row = i4 / BN4;
                const int c = (i4 - row * BN4) * 4;
                rb[t] = *reinterpret_cast<const float4*>(W + (size_t)(kt + row) * Cout + n0 + c);
            }
        }
    };
    auto store_tile = [&](int buf) {
#pragma unroll
        for (int t = 0; t < NA; ++t) {
            const int i4 = tid + t * THREADS;
            if (i4 < A4) {
                const int row = i4 / BK4;
                const int c4 = (i4 - row * BK4) * 4;
                As[buf][c4 + 0][row] = ra[t].x;
                As[buf][c4 + 1][row] = ra[t].y;
                As[buf][c4 + 2][row] = ra[t].z;
                As[buf][c4 + 3][row] = ra[t].w;
            }
        }
#pragma unroll
        for (int t = 0; t < NB; ++t) {
            const int i4 = tid + t * THREADS;
            if (i4 < B4) {
                const int row = i4 / BN4;
                const int c = (i4 - row * BN4) * 4;
                *reinterpret_cast<float4*>(&Bs[buf][row][c]) = rb[t];
            }
        }
    };

    load_tile(0); store_tile(0); __syncthreads();
    int buf = 0;
    for (int it = 0; it < ntile; ++it) {
        if (it + 1 < ntile) load_tile(it + 1);
#pragma unroll
        for (int kk = 0; kk < BK; ++kk) {
            float a[TM], b[TN];
#pragma unroll
            for (int i = 0; i < TM; i += 4) {
                const float4 v = *reinterpret_cast<const float4*>(&As[buf][kk][ty * TM + i]);
                a[i] = v.x; a[i + 1] = v.y; a[i + 2] = v.z; a[i + 3] = v.w;
            }
#pragma unroll
            for (int j = 0; j < TN; j += 4) {
                const float4 v = *reinterpret_cast<const float4*>(&Bs[buf][kk][tx * TN + j]);
                b[j] = v.x; b[j + 1] = v.y; b[j + 2] = v.z; b[j + 3] = v.w;
            }
#pragma unroll
            for (int i = 0; i < TM; ++i)
#pragma unroll
                for (int j = 0; j < TN; ++j)
                    acc[i][j] = fmaf(a[i], b[j], acc[i][j]);
        }
        if (it + 1 < ntile) store_tile(buf ^ 1);
        __syncthreads();
        buf ^= 1;
    }
#pragma unroll
    for (int i = 0; i < TM; ++i) {
        const int mm = m0 + ty * TM + i;
        if (mm >= M) continue;
        const int bb = mm >> 10, ss = mm & 1023;
#pragma unroll
        for (int j = 0; j < TN; ++j) {
            const int n = n0 + tx * TN + j;
            out[((size_t)bb * Cout + n) * 1024 + ss] = acc[i][j];
        }
    }
}

// Stem: Cin=3 -> dedicated SIMT kernel; writes fp32 + interleaved bf16.
__global__ __launch_bounds__(256) void stem_k(
    const float* __restrict__ feats, const int* __restrict__ nbr,
    const float* __restrict__ W, float* __restrict__ out,
    uint4* __restrict__ outI, int M)
{
    __shared__ float sW[27 * 3 * 32];
    __shared__ float sg[8][81];
    __shared__ int   sidx[8][27];
    const int tid = threadIdx.x;
    const int m0 = blockIdx.x * 8;

    for (int i = tid; i < 27 * 96; i += 256) sW[i] = W[i];
    for (int i = tid; i < 8 * 27; i += 256) {
        const int r = i / 27, k = i % 27;
        const int m = m0 + r;
        sidx[r][k] = (m < M) ? nbr[(size_t)m * 27 + k] : 0;
    }
    __syncthreads();
    for (int i = tid; i < 8 * 81; i += 256) {
        const int r = i / 81, j = i % 81;
        sg[r][j] = feats[(size_t)sidx[r][j / 3] * 3 + (j % 3)];
    }
    __syncthreads();
    const int r = tid >> 5, co = tid & 31;
    const int m = m0 + r;
    float acc = 0.f;
#pragma unroll
    for (int j = 0; j < 81; ++j)
        acc = fmaf(sg[r][j], sW[j * 32 + co], acc);
    if (m < M) {
        const float v = fmaxf(acc, 0.f);
        out[(size_t)m * 32 + co] = v;
        const __nv_bfloat16 h = __float2bfloat16_rn(v);
        const __nv_bfloat16 l = __float2bfloat16_rn(v - __bfloat162float(h));
        __nv_bfloat16* bi = reinterpret_cast<__nv_bfloat16*>(outI);
        const size_t goff = ((size_t)m * 32 + co) >> 3;
        const int w = co & 7;
        bi[goff * 16 + w] = h;
        bi[goff * 16 + 8 + w] = l;
    }
}

static float* symf(const void* s) { void* p = nullptr; cudaGetSymbolAddress(&p, s); return (float*)p; }
static uint4* sym4(const void* s) { void* p = nullptr; cudaGetSymbolAddress(&p, s); return (uint4*)p; }

extern "C" void kernel_launch(void* const* d_in, const int* in_sizes, int n_in,
                              void* d_out, int out_size)
{
    const float* feats  = (const float*)d_in[0];
    const int* nbr0     = (const int*)d_in[1];
    const int* nbr1     = (const int*)d_in[2];
    const int* nbr2     = (const int*)d_in[3];
    const int* nbr3     = (const int*)d_in[4];
    const int* down1    = (const int*)d_in[5];
    const int* down2    = (const int*)d_in[6];
    const int* down3    = (const int*)d_in[7];
    const int* up2      = (const int*)d_in[8];
    const int* up1      = (const int*)d_in[9];
    const int* up0      = (const int*)d_in[10];
    const int* seed_idx = (const int*)d_in[11];
    const float* W_stem = (const float*)d_in[12];
    const float* W_b0   = (const float*)d_in[13];
    const float* W_d1   = (const float*)d_in[14];
    const float* W_b1   = (const float*)d_in[15];
    const float* W_d2   = (const float*)d_in[16];
    const float* W_b2   = (const float*)d_in[17];
    const float* W_d3   = (const float*)d_in[18];
    const float* W_b3   = (const float*)d_in[19];
    const float* W_u2   = (const float*)d_in[20];
    const float* W_u1   = (const float*)d_in[21];
    const float* W_u0   = (const float*)d_in[22];
    const float* W_out  = (const float*)d_in[23];
    float* out = (float*)d_out;

    float* x0a_f = symf(g_x0a_f); float* x1a_f = symf(g_x1a_f);
    float* x2a_f = symf(g_x2a_f); float* x3a_f = symf(g_x3a_f);
    float* u0_f  = symf(g_u0_f);
    uint4* x0a_i = sym4(g_x0a_i); uint4* x0b_i = sym4(g_x0b_i);
    uint4* x1a_i = sym4(g_x1a_i); uint4* x1b_i = sym4(g_x1b_i);
    uint4* x2a_i = sym4(g_x2a_i); uint4* x2b_i = sym4(g_x2b_i);
    uint4* x3a_i = sym4(g_x3a_i); uint4* x3b_i = sym4(g_x3b_i);
    uint4* u2_i  = sym4(g_u2_i);  uint4* u1_i  = sym4(g_u1_i);

    const int SM32  = (2 * 128 * 128 + 2 * 32 * 128) * 2 + 1024;
    const int SM64  = (2 * 128 * 128 + 2 * 64 * 128) * 2 + 1024;
    const int SM128 = (2 * 128 * 128 + 2 * 128 * 128) * 2 + 1024;
    const int SM256 = (2 * 128 * 128 + 2 * 256 * 128) * 2 + 1024;
    cudaFuncSetAttribute(tc_gemm<32,  A_CONV,   E_RES_RELU>, cudaFuncAttributeMaxDynamicSharedMemorySize, SM32);
    cudaFuncSetAttribute(tc_gemm<64,  A_CONV,   E_RELU>,     cudaFuncAttributeMaxDynamicSharedMemorySize, SM64);
    cudaFuncSetAttribute(tc_gemm<64,  A_CONV,   E_RES_RELU>, cudaFuncAttributeMaxDynamicSharedMemorySize, SM64);
    cudaFuncSetAttribute(tc_gemm<128, A_CONV,   E_RELU>,     cudaFuncAttributeMaxDynamicSharedMemorySize, SM128);
    cudaFuncSetAttribute(tc_gemm<128, A_CONV,   E_RES_RELU>, cudaFuncAttributeMaxDynamicSharedMemorySize, SM128);
    cudaFuncSetAttribute(tc_gemm<128, A_CONCAT, E_RELU>,     cudaFuncAttributeMaxDynamicSharedMemorySize, SM128);
    cudaFuncSetAttribute(tc_gemm<256, A_CONV,   E_RELU>,     cudaFuncAttributeMaxDynamicSharedMemorySize, SM256);
    cudaFuncSetAttribute(tc_gemm<256, A_CONV,   E_RES_RELU>, cudaFuncAttributeMaxDynamicSharedMemorySize, SM256);
    cudaFuncSetAttribute(tc_gemm<256, A_CONCAT, E_RELU>,     cudaFuncAttributeMaxDynamicSharedMemorySize, SM256);

    auto cw = [&](const float* W, uint4* Wh, uint4* Wl, int Kd, int Co, int Kp, int Np) {
        const int total = Np * Kp;
        conv_w<<<(total + 255) / 256, 256>>>(W, Wh, Wl, Kd, Co, Kp, Np);
    };

    const int M0 = KN0, M1 = KN1, M2 = KN2, M3 = KN3;
    auto g = [](int M) { return (unsigned)((M + 127) / 128); };

    // Launch order arranged so ncu -s 5 -c 1 samples tc_gemm (tc_b0) instead
    // of conv_w: [0..3] conv_w, [4] stem, [5] tc_b0, then the rest.
    cw(W_b0, sym4(w_b0h), sym4(w_b0l),  864,  32,  896,  32);     // 0
    cw(W_d1, sym4(w_d1h), sym4(w_d1l),  256,  64,  256,  64);     // 1
    cw(W_b1, sym4(w_b1h), sym4(w_b1l), 1728,  64, 1728,  64);     // 2
    cw(W_d2, sym4(w_d2h), sym4(w_d2l),  512, 128,  512, 128);     // 3

    stem_k<<<(M0 + 7) / 8, 256>>>(feats, nbr0, W_stem, x0a_f, x0a_i, M0);  // 4

    tc_gemm<32, A_CONV, E_RES_RELU><<<g(M0), 256, SM32>>>(                  // 5
        x0a_i, nullptr, nbr0, sym4(w_b0h), sym4(w_b0l), x0a_f, nullptr, x0b_i,
        M0, 32, 864, 896, 32, 27, 0);

    cw(W_b2, sym4(w_b2h), sym4(w_b2l), 3456, 128, 3456, 128);
    cw(W_d3, sym4(w_d3h), sym4(w_d3l), 1024, 256, 1024, 256);
    cw(W_b3, sym4(w_b3h), sym4(w_b3l), 6912, 256, 6912, 256);
    cw(W_u2, sym4(w_u2h), sym4(w_u2l),  384, 256,  384, 256);
    cw(W_u1, sym4(w_u1h), sym4(w_u1l),  320, 128,  320, 128);
    cw(W_u0, sym4(w_u0h), sym4(w_u0l),  160,  96,  192, 128);

    tc_gemm<64, A_CONV, E_RELU><<<g(M1), 256, SM64>>>(
        x0b_i, nullptr, down1, sym4(w_d1h), sym4(w_d1l), nullptr, x1a_f, x1a_i,
        M1, 64, 256, 256, 32, 8, 0);
    tc_gemm<64, A_CONV, E_RES_RELU><<<g(M1), 256, SM64>>>(
        x1a_i, nullptr, nbr1, sym4(w_b1h), sym4(w_b1l), x1a_f, nullptr, x1b_i,
        M1, 64, 1728, 1728, 64, 27, 0);

    tc_gemm<128, A_CONV, E_RELU><<<g(M2), 256, SM128>>>(
        x1b_i, nullptr, down2, sym4(w_d2h), sym4(w_d2l), nullptr, x2a_f, x2a_i,
        M2, 128, 512, 512, 64, 8, 0);
    tc_gemm<128, A_CONV, E_RES_RELU><<<g(M2), 256, SM128>>>(
        x2a_i, nullptr, nbr2, sym4(w_b2h), sym4(w_b2l), x2a_f, nullptr, x2b_i,
        M2, 128, 3456, 3456, 128, 27, 0);

    tc_gemm<256, A_CONV, E_RELU><<<g(M3), 256, SM256>>>(
        x2b_i, nullptr, down3, sym4(w_d3h), sym4(w_d3l), nullptr, x3a_f, x3a_i,
        M3, 256, 1024, 1024, 128, 8, 0);
    tc_gemm<256, A_CONV, E_RES_RELU><<<g(M3), 256, SM256>>>(
        x3a_i, nullptr, nbr3, sym4(w_b3h), sym4(w_b3l), x3a_f, nullptr, x3b_i,
        M3, 256, 6912, 6912, 256, 27, 0);

    // ---- decoder ----
    tc_gemm<256, A_CONCAT, E_RELU><<<g(M2), 256, SM256>>>(
        x3b_i, x2b_i, up2, sym4(w_u2h), sym4(w_u2l), nullptr, nullptr, u2_i,
        M2, 256, 384, 384, 0, 0, 256);
    tc_gemm<128, A_CONCAT, E_RELU><<<g(M1), 256, SM128>>>(
        u2_i, x1b_i, up1, sym4(w_u1h), sym4(w_u1l), nullptr, nullptr, u1_i,
        M1, 128, 320, 320, 0, 0, 256);
    tc_gemm<128, A_CONCAT, E_RELU><<<g(M0), 256, SM128>>>(
        u1_i, x0b_i, up0, sym4(w_u0h), sym4(w_u0l), nullptr, u0_f, nullptr,
        M0, 96, 160, 192, 0, 0, 128);

    // ---- final: gather 8192 seed rows, project to 512, transpose-store ----
    gemm_final<128, 128, 16, 8, 8><<<dim3(64, 4), 256>>>(
        u0_f, seed_idx, W_out, out, 8 * 1024, 512, 96);
}